// round 11
// baseline (speedup 1.0000x reference)
#include <cuda_runtime.h>
#include <cstdint>
#include <cstddef>

#define Bn 32
#define Fd 512
#define Td 2000
#define Ed 256
#define Hd 128
#define EPSf 1e-7f

// ---------------- static device scratch ----------------
__device__ float g_enc [ (size_t)Bn*Td*Ed ];
__device__ float g_zpre[ (size_t)Bn*Td*4*Hd ];   // reused as est
__device__ float g_ys2 [ (size_t)Bn*Td*Hd ];
__device__ float g_mean[ Bn*Td ];
__device__ float g_rstd[ Bn*Td ];
__device__ float g_encwT[ Fd*Ed ];
__device__ float g_W1gT [ Ed*4*Hd ];
__device__ float g_decwT[ Ed*Fd ];
__device__ float g_WdT  [ Hd*Ed ];
__device__ float g_bias1[ 4*Hd ];
__device__ float g_bias2[ 4*Hd ];

typedef unsigned long long u64;

__device__ __forceinline__ float sigf(float x){ return 1.0f/(1.0f + expf(-x)); }
__device__ __forceinline__ float ftanh(float x){ float y; asm("tanh.approx.f32 %0, %1;" : "=f"(y) : "f"(x)); return y; }
__device__ __forceinline__ float fsig(float x){ return fmaf(ftanh(0.5f*x), 0.5f, 0.5f); }

__device__ __forceinline__ void ffma2(u64& d, u64 a, u64 b){
    asm("fma.rn.f32x2 %0, %1, %2, %0;" : "+l"(d) : "l"(a), "l"(b));
}
__device__ __forceinline__ u64 packdup(float a){
    u64 r; asm("mov.b64 %0, {%1, %1};" : "=l"(r) : "f"(a)); return r;
}
__device__ __forceinline__ void unpk(float& lo, float& hi, u64 v){
    asm("mov.b64 {%0, %1}, %2;" : "=f"(lo), "=f"(hi) : "l"(v));
}
__device__ __forceinline__ float upsum(u64 a, u64 b){
    float x,y,z,w; unpk(x,y,a); unpk(z,w,b); return (x+y)+(z+w);
}

__device__ __forceinline__ uint32_t smem_u32(const void* p){ return (uint32_t)__cvta_generic_to_shared(p); }
__device__ __forceinline__ uint32_t mapa_rank(uint32_t laddr, uint32_t r){
    uint32_t ra; asm("mapa.shared::cluster.u32 %0, %1, %2;" : "=r"(ra) : "r"(laddr), "r"(r)); return ra;
}
__device__ __forceinline__ void st_async_f32(uint32_t dst, float v, uint32_t rbar){
    asm volatile("st.async.shared::cluster.mbarrier::complete_tx::bytes.f32 [%0], %1, [%2];"
                 :: "r"(dst), "f"(v), "r"(rbar) : "memory");
}
__device__ __forceinline__ void mbar_init(uint32_t a, uint32_t cnt){
    asm volatile("mbarrier.init.shared.b64 [%0], %1;" :: "r"(a), "r"(cnt) : "memory");
}
__device__ __forceinline__ void mbar_arrive_expect(uint32_t a, uint32_t bytes){
    asm volatile("mbarrier.arrive.expect_tx.shared.b64 _, [%0], %1;" :: "r"(a), "r"(bytes) : "memory");
}
__device__ __forceinline__ void mbar_arrive_remote(uint32_t laddr, uint32_t r){
    uint32_t ra = mapa_rank(laddr, r);
    asm volatile("mbarrier.arrive.shared::cluster.b64 _, [%0];" :: "r"(ra) : "memory");
}
__device__ __forceinline__ void mbar_wait(uint32_t a, int ph){
    asm volatile(
        "{\n\t.reg .pred P;\n\t"
        "WL_%=:\n\t"
        "mbarrier.try_wait.parity.acquire.cta.shared::cta.b64 P, [%0], %1, 0x989680;\n\t"
        "@P bra.uni WD_%=;\n\t"
        "bra.uni WL_%=;\n\t"
        "WD_%=:\n\t}"
        :: "r"(a), "r"((uint32_t)ph) : "memory");
}
__device__ __forceinline__ void cluster_sync(){
    asm volatile("barrier.cluster.arrive.aligned;" ::: "memory");
    asm volatile("barrier.cluster.wait.aligned;" ::: "memory");
}

// ---------------- prep ----------------
__global__ void prep_kernel(const float* __restrict__ enc_w, const float* __restrict__ gamma,
                            const float* __restrict__ beta,  const float* __restrict__ Wih1,
                            const float* __restrict__ dec_w, const float* __restrict__ Wd,
                            const float* __restrict__ bih1,  const float* __restrict__ bhh1,
                            const float* __restrict__ bih2,  const float* __restrict__ bhh2)
{
    int i = blockIdx.x*blockDim.x + threadIdx.x;
    int n = gridDim.x*blockDim.x;
    for (int idx=i; idx<Fd*Ed; idx+=n){ int f=idx/Ed, e=idx%Ed; g_encwT[idx] = enc_w[e*Fd + f]; }
    for (int idx=i; idx<Ed*4*Hd; idx+=n){ int e=idx>>9, j=idx&511; g_W1gT[idx] = Wih1[j*Ed + e]*gamma[e]; }
    for (int idx=i; idx<Ed*Fd; idx+=n){ int e=idx>>9, f=idx&511; g_decwT[idx] = dec_w[f*Ed + e]; }
    for (int idx=i; idx<Hd*Ed; idx+=n){ int h=idx>>8, e=idx&255; g_WdT[idx] = Wd[e*Hd + h]; }
    for (int j=i; j<4*Hd; j+=n) g_bias2[j] = bih2[j] + bhh2[j];
    int wid = i >> 5, lane = i & 31;
    for (int j=wid; j<4*Hd; j += n>>5){
        float s = 0.f;
        for (int e=lane; e<Ed; e+=32) s += beta[e]*Wih1[j*Ed + e];
        #pragma unroll
        for (int o=16;o>0;o>>=1) s += __shfl_xor_sync(0xffffffffu, s, o);
        if (lane==0) g_bias1[j] = s + bih1[j] + bhh1[j];
    }
}

// ---------------- enc GEMM (R7 proven) ----------------
__global__ void __launch_bounds__(256) enc_kernel(const float* __restrict__ y1)
{
    __shared__ __align__(16) float As[2][16][128];
    __shared__ __align__(16) float Bs[2][16][64];
    const int b = blockIdx.z;
    const int t0 = blockIdx.x*128, e0 = blockIdx.y*64;
    const int tid = threadIdx.x;
    const int lk = tid>>4, lt = (tid&15)*8;
    const int bk = tid>>4, bn = (tid&15)*4;
    const int ty = tid>>4, tx = tid&15;
    const float* yb = y1 + (size_t)b*Fd*Td;
    u64 acc[8][2] = {};
    float4 ra0, ra1, rb0;
    {
        int t = t0 + lt;
        ra0 = make_float4(0.f,0.f,0.f,0.f); ra1 = ra0;
        if (t   < Td) ra0 = *(const float4*)(yb + (size_t)lk*Td + t);
        if (t+4 < Td) ra1 = *(const float4*)(yb + (size_t)lk*Td + t + 4);
        rb0 = *(const float4*)(g_encwT + (size_t)bk*Ed + e0 + bn);
        *(float4*)&As[0][lk][lt]   = ra0;
        *(float4*)&As[0][lk][lt+4] = ra1;
        *(float4*)&Bs[0][bk][bn]   = rb0;
    }
    __syncthreads();
    int cur = 0;
    for (int k0=0;k0<Fd;k0+=16){
        const bool more = (k0+16 < Fd);
        if (more){
            int k = k0 + 16 + lk;
            int t = t0 + lt;
            ra0 = make_float4(0.f,0.f,0.f,0.f); ra1 = ra0;
            if (t   < Td) ra0 = *(const float4*)(yb + (size_t)k*Td + t);
            if (t+4 < Td) ra1 = *(const float4*)(yb + (size_t)k*Td + t + 4);
            rb0 = *(const float4*)(g_encwT + (size_t)(k0+16+bk)*Ed + e0 + bn);
        }
        #pragma unroll
        for (int kk=0;kk<16;kk++){
            ulonglong2 bp = *(const ulonglong2*)&Bs[cur][kk][tx*4];
            float4 a0 = *(const float4*)&As[cur][kk][ty*8];
            float4 a1 = *(const float4*)&As[cur][kk][ty*8+4];
            u64 d0=packdup(a0.x), d1=packdup(a0.y), d2=packdup(a0.z), d3=packdup(a0.w);
            u64 d4=packdup(a1.x), d5=packdup(a1.y), d6=packdup(a1.z), d7=packdup(a1.w);
            ffma2(acc[0][0],d0,bp.x); ffma2(acc[0][1],d0,bp.y);
            ffma2(acc[1][0],d1,bp.x); ffma2(acc[1][1],d1,bp.y);
            ffma2(acc[2][0],d2,bp.x); ffma2(acc[2][1],d2,bp.y);
            ffma2(acc[3][0],d3,bp.x); ffma2(acc[3][1],d3,bp.y);
            ffma2(acc[4][0],d4,bp.x); ffma2(acc[4][1],d4,bp.y);
            ffma2(acc[5][0],d5,bp.x); ffma2(acc[5][1],d5,bp.y);
            ffma2(acc[6][0],d6,bp.x); ffma2(acc[6][1],d6,bp.y);
            ffma2(acc[7][0],d7,bp.x); ffma2(acc[7][1],d7,bp.y);
        }
        if (more){
            int nb = cur^1;
            *(float4*)&As[nb][lk][lt]   = ra0;
            *(float4*)&As[nb][lk][lt+4] = ra1;
            *(float4*)&Bs[nb][bk][bn]   = rb0;
        }
        __syncthreads();
        cur ^= 1;
    }
    #pragma unroll
    for (int i=0;i<8;i++){
        int t = t0 + ty*8 + i;
        if (t < Td){
            float4 v;
            unpk(v.x, v.y, acc[i][0]);
            unpk(v.z, v.w, acc[i][1]);
            *(float4*)(g_enc + ((size_t)b*Td + t)*Ed + e0 + tx*4) = v;
        }
    }
}

// ---------------- layernorm stats ----------------
__global__ void __launch_bounds__(256) ln_kernel()
{
    int row = blockIdx.x*8 + (threadIdx.x>>5);
    int lane = threadIdx.x & 31;
    const float* p = g_enc + (size_t)row*Ed;
    float4 a = *(const float4*)(p + lane*4);
    float4 c = *(const float4*)(p + 128 + lane*4);
    float s = a.x+a.y+a.z+a.w + c.x+c.y+c.z+c.w;
    #pragma unroll
    for (int o=16;o>0;o>>=1) s += __shfl_xor_sync(0xffffffffu, s, o);
    float mean = s * (1.0f/256.0f);
    float d, sq = 0.f;
    d=a.x-mean; sq+=d*d; d=a.y-mean; sq+=d*d; d=a.z-mean; sq+=d*d; d=a.w-mean; sq+=d*d;
    d=c.x-mean; sq+=d*d; d=c.y-mean; sq+=d*d; d=c.z-mean; sq+=d*d; d=c.w-mean; sq+=d*d;
    #pragma unroll
    for (int o=16;o>0;o>>=1) sq += __shfl_xor_sync(0xffffffffu, sq, o);
    if (lane==0){
        g_mean[row] = mean;
        g_rstd[row] = rsqrtf(sq*(1.0f/256.0f) + EPSf);
    }
}

// ---------------- GEMM modes 0/1 (R7 proven) ----------------
__global__ void __launch_bounds__(256) gemm_kernel(
    const float* __restrict__ A, const float* __restrict__ Bm, float* __restrict__ C,
    const float* __restrict__ bias, const float* __restrict__ meanp, const float* __restrict__ rstdp,
    const float* __restrict__ encp, int K, int N, int mode)
{
    __shared__ __align__(16) float As[2][16][128];
    __shared__ __align__(16) float Bs[2][16][64];
    const int tid = threadIdx.x;
    const int m0 = blockIdx.x*128, n0 = blockIdx.y*64;
    const int ar = tid>>1, ak = (tid&1)*8;
    const int bk = tid>>4, bn = (tid&15)*4;
    const int ty = tid>>4, tx = tid&15;
    float mu=0.f, rs=1.f;
    if (mode==0){ mu = meanp[m0+ar]; rs = rstdp[m0+ar]; }
    const float* Arow = A + (size_t)(m0+ar)*K;
    u64 acc[8][2] = {};
    float4 ra0, ra1, rb0;
    {
        ra0 = *(const float4*)(Arow + ak);
        ra1 = *(const float4*)(Arow + ak + 4);
        if (mode==0){
            ra0.x=(ra0.x-mu)*rs; ra0.y=(ra0.y-mu)*rs; ra0.z=(ra0.z-mu)*rs; ra0.w=(ra0.w-mu)*rs;
            ra1.x=(ra1.x-mu)*rs; ra1.y=(ra1.y-mu)*rs; ra1.z=(ra1.z-mu)*rs; ra1.w=(ra1.w-mu)*rs;
        }
        rb0 = *(const float4*)(Bm + (size_t)bk*N + n0 + bn);
        As[0][ak+0][ar]=ra0.x; As[0][ak+1][ar]=ra0.y; As[0][ak+2][ar]=ra0.z; As[0][ak+3][ar]=ra0.w;
        As[0][ak+4][ar]=ra1.x; As[0][ak+5][ar]=ra1.y; As[0][ak+6][ar]=ra1.z; As[0][ak+7][ar]=ra1.w;
        *(float4*)&Bs[0][bk][bn] = rb0;
    }
    __syncthreads();
    int cur = 0;
    for (int k0=0;k0<K;k0+=16){
        const bool more = (k0+16 < K);
        if (more){
            ra0 = *(const float4*)(Arow + k0+16 + ak);
            ra1 = *(const float4*)(Arow + k0+16 + ak + 4);
            if (mode==0){
                ra0.x=(ra0.x-mu)*rs; ra0.y=(ra0.y-mu)*rs; ra0.z=(ra0.z-mu)*rs; ra0.w=(ra0.w-mu)*rs;
                ra1.x=(ra1.x-mu)*rs; ra1.y=(ra1.y-mu)*rs; ra1.z=(ra1.z-mu)*rs; ra1.w=(ra1.w-mu)*rs;
            }
            rb0 = *(const float4*)(Bm + (size_t)(k0+16+bk)*N + n0 + bn);
        }
        #pragma unroll
        for (int kk=0;kk<16;kk++){
            ulonglong2 bp = *(const ulonglong2*)&Bs[cur][kk][tx*4];
            float4 a0 = *(const float4*)&As[cur][kk][ty*8];
            float4 a1 = *(const float4*)&As[cur][kk][ty*8+4];
            u64 d0=packdup(a0.x), d1=packdup(a0.y), d2=packdup(a0.z), d3=packdup(a0.w);
            u64 d4=packdup(a1.x), d5=packdup(a1.y), d6=packdup(a1.z), d7=packdup(a1.w);
            ffma2(acc[0][0],d0,bp.x); ffma2(acc[0][1],d0,bp.y);
            ffma2(acc[1][0],d1,bp.x); ffma2(acc[1][1],d1,bp.y);
            ffma2(acc[2][0],d2,bp.x); ffma2(acc[2][1],d2,bp.y);
            ffma2(acc[3][0],d3,bp.x); ffma2(acc[3][1],d3,bp.y);
            ffma2(acc[4][0],d4,bp.x); ffma2(acc[4][1],d4,bp.y);
            ffma2(acc[5][0],d5,bp.x); ffma2(acc[5][1],d5,bp.y);
            ffma2(acc[6][0],d6,bp.x); ffma2(acc[6][1],d6,bp.y);
            ffma2(acc[7][0],d7,bp.x); ffma2(acc[7][1],d7,bp.y);
        }
        if (more){
            int nb = cur^1;
            As[nb][ak+0][ar]=ra0.x; As[nb][ak+1][ar]=ra0.y; As[nb][ak+2][ar]=ra0.z; As[nb][ak+3][ar]=ra0.w;
            As[nb][ak+4][ar]=ra1.x; As[nb][ak+5][ar]=ra1.y; As[nb][ak+6][ar]=ra1.z; As[nb][ak+7][ar]=ra1.w;
            *(float4*)&Bs[nb][bk][bn] = rb0;
        }
        __syncthreads();
        cur ^= 1;
    }
    float4 bv = make_float4(0.f,0.f,0.f,0.f);
    if (bias) bv = *(const float4*)(bias + n0 + tx*4);
    #pragma unroll
    for (int i=0;i<8;i++){
        int m = m0 + ty*8 + i;
        float4 v;
        unpk(v.x, v.y, acc[i][0]);
        unpk(v.z, v.w, acc[i][1]);
        v.x += bv.x; v.y += bv.y; v.z += bv.z; v.w += bv.w;
        if (mode==1){
            float4 e = *(const float4*)(encp + (size_t)m*N + n0 + tx*4);
            v.x = sigf(v.x)*e.x; v.y = sigf(v.y)*e.y; v.z = sigf(v.z)*e.z; v.w = sigf(v.w)*e.w;
        }
        *(float4*)(C + (size_t)m*N + n0 + tx*4) = v;
    }
}

// ---------------- decode GEMM (R7 proven) ----------------
__global__ void __launch_bounds__(256) dec_kernel(const float* __restrict__ A, float* __restrict__ C)
{
    __shared__ float buf[8256];
    float* AsB = buf;
    float* BsB = buf + 4096;
    const int b  = blockIdx.z;
    const int m0 = blockIdx.x*128;
    const int n0 = blockIdx.y*64;
    const int tid = threadIdx.x;
    const int ar = tid>>1, ak = (tid&1)*8;
    const int bk = tid>>4, bn = (tid&15)*4;
    const int ty = tid>>4, tx = tid&15;
    const float* Arow = A + ((size_t)b*Td + m0 + ar)*Ed;
    u64 acc[8][2] = {};
    float4 ra0, ra1, rb0;
    {
        ra0 = *(const float4*)(Arow + ak);
        ra1 = *(const float4*)(Arow + ak + 4);
        rb0 = *(const float4*)(g_decwT + (size_t)bk*Fd + n0 + bn);
        AsB[(ak+0)*128+ar]=ra0.x; AsB[(ak+1)*128+ar]=ra0.y; AsB[(ak+2)*128+ar]=ra0.z; AsB[(ak+3)*128+ar]=ra0.w;
        AsB[(ak+4)*128+ar]=ra1.x; AsB[(ak+5)*128+ar]=ra1.y; AsB[(ak+6)*128+ar]=ra1.z; AsB[(ak+7)*128+ar]=ra1.w;
        *(float4*)&BsB[bk*64 + bn] = rb0;
    }
    __syncthreads();
    int cur = 0;
    for (int k0=0;k0<Ed;k0+=16){
        const bool more = (k0+16 < Ed);
        if (more){
            ra0 = *(const float4*)(Arow + k0+16 + ak);
            ra1 = *(const float4*)(Arow + k0+16 + ak + 4);
            rb0 = *(const float4*)(g_decwT + (size_t)(k0+16+bk)*Fd + n0 + bn);
        }
        const float* asb = &AsB[cur*2048];
        const float* bsb = &BsB[cur*1024];
        #pragma unroll
        for (int kk=0;kk<16;kk++){
            ulonglong2 bp = *(const ulonglong2*)&bsb[kk*64 + tx*4];
            float4 a0 = *(const float4*)&asb[kk*128 + ty*8];
            float4 a1 = *(const float4*)&asb[kk*128 + ty*8 + 4];
            u64 d0=packdup(a0.x), d1=packdup(a0.y), d2=packdup(a0.z), d3=packdup(a0.w);
            u64 d4=packdup(a1.x), d5=packdup(a1.y), d6=packdup(a1.z), d7=packdup(a1.w);
            ffma2(acc[0][0],d0,bp.x); ffma2(acc[0][1],d0,bp.y);
            ffma2(acc[1][0],d1,bp.x); ffma2(acc[1][1],d1,bp.y);
            ffma2(acc[2][0],d2,bp.x); ffma2(acc[2][1],d2,bp.y);
            ffma2(acc[3][0],d3,bp.x); ffma2(acc[3][1],d3,bp.y);
            ffma2(acc[4][0],d4,bp.x); ffma2(acc[4][1],d4,bp.y);
            ffma2(acc[5][0],d5,bp.x); ffma2(acc[5][1],d5,bp.y);
            ffma2(acc[6][0],d6,bp.x); ffma2(acc[6][1],d6,bp.y);
            ffma2(acc[7][0],d7,bp.x); ffma2(acc[7][1],d7,bp.y);
        }
        if (more){
            int nb = cur^1;
            float* ap = &AsB[nb*2048];
            ap[(ak+0)*128+ar]=ra0.x; ap[(ak+1)*128+ar]=ra0.y; ap[(ak+2)*128+ar]=ra0.z; ap[(ak+3)*128+ar]=ra0.w;
            ap[(ak+4)*128+ar]=ra1.x; ap[(ak+5)*128+ar]=ra1.y; ap[(ak+6)*128+ar]=ra1.z; ap[(ak+7)*128+ar]=ra1.w;
            *(float4*)&BsB[nb*1024 + bk*64 + bn] = rb0;
        }
        __syncthreads();
        cur ^= 1;
    }
    __syncthreads();
    #pragma unroll
    for (int i=0;i<8;i++){
        float v0,v1,v2,v3;
        unpk(v0,v1,acc[i][0]); unpk(v2,v3,acc[i][1]);
        int ml = ty*8 + i;
        buf[(tx*4+0)*129 + ml] = v0;
        buf[(tx*4+1)*129 + ml] = v1;
        buf[(tx*4+2)*129 + ml] = v2;
        buf[(tx*4+3)*129 + ml] = v3;
    }
    __syncthreads();
    {
        int f = tid>>2;
        int seg = (tid&3)*32;
        float* crow = C + ((size_t)b*Fd + n0 + f)*Td;
        const float* trow = &buf[f*129 + seg];
        #pragma unroll
        for (int q=0;q<8;q++){
            int t = m0 + seg + q*4;
            if (t < Td){
                float4 v = make_float4(trow[q*4+0], trow[q*4+1], trow[q*4+2], trow[q*4+3]);
                *(float4*)(crow + t) = v;
            }
        }
    }
}

// ---------------- LSTM scan v5: warp-specialized decoupled layers ----------------
// G1 (warps 0-3):  zp1 = Whh1(row)·ys1[s-1], gates -> ys1[s] broadcast (M1, E1 credit)
// G2a (warps 4-7): zp2a = Wih2(row)·ys1[t]
// G2b (warps 8-11): zp2b = Whh2(row)·h2[t-1] + b2, gates by warp4 -> h2[t] (M2)
// ys1[s] lives in h1b[s&1]; h2[t] in h2b[t&1]; initial states in buf 1.
__global__ void __launch_bounds__(384,1) __cluster_dims__(4,1,1)
lstm_kernel(const float* __restrict__ in_state2,
            const float* __restrict__ Whh1, const float* __restrict__ Wih2,
            const float* __restrict__ Whh2, float* __restrict__ out_state)
{
    __shared__ __align__(16) u64 mbM1[2], mbM2[2], mbE1[2];
    __shared__ __align__(16) float h1b[2][128];
    __shared__ __align__(16) float h2b[2][128];
    __shared__ __align__(16) float zp1[128];
    __shared__ __align__(16) float zp2a[2][128];
    __shared__ __align__(16) float zp2b[2][128];

    const int tid  = threadIdx.x;
    const int rank = blockIdx.x & 3, b = blockIdx.x >> 2;
    const int grp  = tid >> 7, gidx = tid & 127;
    const int Rg = (gidx>>5)*128 + rank*32 + (gidx&31);

    uint32_t m1a[2] = { smem_u32(&mbM1[0]), smem_u32(&mbM1[1]) };
    uint32_t m2a[2] = { smem_u32(&mbM2[0]), smem_u32(&mbM2[1]) };
    uint32_t e1a[2] = { smem_u32(&mbE1[0]), smem_u32(&mbE1[1]) };

    if (tid == 0){
        #pragma unroll
        for (int s=0;s<2;s++){
            mbar_init(m1a[s], 1); mbar_arrive_expect(m1a[s], 512);
            mbar_init(m2a[s], 1); mbar_arrive_expect(m2a[s], 512);
            mbar_init(e1a[s], 4);
        }
    }

    // full weight row in registers: 128 floats = 64 u64
    u64 W[64];
    {
        const float* pW = (grp==0 ? Whh1 : (grp==1 ? Wih2 : Whh2)) + (size_t)Rg*Hd;
        const u64* q = (const u64*)pW;
        #pragma unroll
        for (int k=0;k<64;k++) W[k] = q[k];
    }
    if (grp == 0){
        h1b[1][gidx] = in_state2[(((size_t)0*Bn + b)*Hd + gidx)*2 + 0];
        h2b[1][gidx] = in_state2[(((size_t)1*Bn + b)*Hd + gidx)*2 + 0];
    }
    const float b2r = g_bias2[Rg];

    float c1=0.f, c2=0.f, h1v=0.f, h2v=0.f;
    int hh = 0;
    const bool g1gate = (tid < 32);
    const bool g2gate = (tid >= 128 && tid < 160);
    uint32_t dst[2][4], rb[2][4];
    if (g1gate){
        hh = rank*32 + tid;
        uint32_t la = smem_u32(&h1b[0][hh]);
        #pragma unroll
        for (int s=0;s<2;s++)
            #pragma unroll
            for (int r=0;r<4;r++){ dst[s][r] = mapa_rank(la + s*512, (uint32_t)r); rb[s][r] = mapa_rank(m1a[s], (uint32_t)r); }
        c1 = in_state2[(((size_t)0*Bn + b)*Hd + hh)*2 + 1];
    }
    if (g2gate){
        hh = rank*32 + (tid - 128);
        uint32_t la = smem_u32(&h2b[0][hh]);
        #pragma unroll
        for (int s=0;s<2;s++)
            #pragma unroll
            for (int r=0;r<4;r++){ dst[s][r] = mapa_rank(la + s*512, (uint32_t)r); rb[s][r] = mapa_rank(m2a[s], (uint32_t)r); }
        c2 = in_state2[(((size_t)1*Bn + b)*Hd + hh)*2 + 1];
    }
    __syncthreads();
    cluster_sync();
    // pre-arm E1 credits (both buffers free)
    if (tid == 0){
        #pragma unroll
        for (int r=0;r<4;r++){ mbar_arrive_remote(e1a[0], (uint32_t)r); mbar_arrive_remote(e1a[1], (uint32_t)r); }
    }

    if (grp == 0){
        // ---- layer 1 producer ----
        const float* zrow = g_zpre + (size_t)b*Td*512 + Rg;
        float zcur = zrow[0];
        float znxt = __ldg(zrow + 512);
        int phM1[2] = {0,0}, phE1[2] = {0,0};
        for (int s=0;s<Td;s++){
            if (s >= 1){ int w = (s-1)&1; mbar_wait(m1a[w], phM1[w]); phM1[w] ^= 1; }
            const int br = (s==0) ? 1 : ((s-1)&1);
            const ulonglong2* x = (const ulonglong2*)&h1b[br][0];
            u64 a0=0,a1=0,a2=0,a3=0;
            #pragma unroll
            for (int k=0;k<16;k++){
                ulonglong2 p = x[2*k], q = x[2*k+1];
                ffma2(a0, W[4*k+0], p.x);
                ffma2(a1, W[4*k+1], p.y);
                ffma2(a2, W[4*k+2], q.x);
                ffma2(a3, W[4*k+3], q.y);
            }
            zp1[gidx] = upsum(a0,a1) + upsum(a2,a3) + zcur;
            asm volatile("bar.sync 1, 128;" ::: "memory");
            if (g1gate){
                const int bw = s&1;
                mbar_wait(e1a[bw], phE1[bw]); phE1[bw] ^= 1;   // buffer free?
                float zi = zp1[tid], zf = zp1[32+tid], zg = zp1[64+tid], zo = zp1[96+tid];
                c1 = fsig(zf)*c1 + fsig(zi)*ftanh(zg);
                h1v = fsig(zo)*ftanh(c1);
                #pragma unroll
                for (int r=0;r<4;r++) st_async_f32(dst[bw][r], h1v, rb[bw][r]);
            }
            zcur = znxt;
            int sn = s + 2; if (sn > Td-1) sn = Td-1;
            znxt = __ldg(zrow + (size_t)sn*512);
        }
        if (g1gate){
            out_state[(((size_t)0*Bn + b)*Hd + hh)*2 + 0] = h1v;
            out_state[(((size_t)0*Bn + b)*Hd + hh)*2 + 1] = c1;
        }
    } else {
        // ---- layer 2 consumer ----
        float* ys2row = g_ys2 + (size_t)b*Td*Hd;
        int phM1[2] = {0,0}, phM2[2] = {0,0};
        for (int t=0;t<Td;t++){
            const int pb = t&1;
            if (grp == 1){
                mbar_wait(m1a[pb], phM1[pb]); phM1[pb] ^= 1;     // ys1[t]
                if (tid == 128) mbar_arrive_expect(m1a[pb], 512);
                const ulonglong2* x = (const ulonglong2*)&h1b[pb][0];
                u64 a0=0,a1=0,a2=0,a3=0;
                #pragma unroll
                for (int k=0;k<16;k++){
                    ulonglong2 p = x[2*k], q = x[2*k+1];
                    ffma2(a0, W[4*k+0], p.x);
                    ffma2(a1, W[4*k+1], p.y);
                    ffma2(a2, W[4*k+2], q.x);
                    ffma2(a3, W[4*k+3], q.y);
                }
                zp2a[pb][gidx] = upsum(a0,a1) + upsum(a2,a3);
            } else {
                const int br = (t==0) ? 1 : ((t-1)&1);
                if (t >= 1){ int w = (t-1)&1; mbar_wait(m2a[w], phM2[w]); phM2[w] ^= 1;
                             if (tid == 256) mbar_arrive_expect(m2a[w], 512); }
                const ulonglong2* x = (const ulonglong2*)&h2b[br][0];
                u64 a0=0,a1=0,a2=0,a3=0;
                #pragma unroll
                for (int k=0;k<16;k++){
                    ulonglong2 p = x[2*k], q = x[2*k+1];
                    ffma2(a0, W[4*k+0], p.x);
                    ffma2(a1, W[4*k+1], p.y);
                    ffma2(a2, W[4*k+2], q.x);
                    ffma2(a3, W[4*k+3], q.y);
                }
                zp2b[pb][gidx] = upsum(a0,a1) + upsum(a2,a3) + b2r;
            }
            asm volatile("bar.sync 2, 256;" ::: "memory");
            if (g2gate){
                int uu = tid - 128;
                float zi = zp2a[pb][uu]    + zp2b[pb][uu];
                float zf = zp2a[pb][32+uu] + zp2b[pb][32+uu];
                float zg = zp2a[pb][64+uu] + zp2b[pb][64+uu];
                float zo = zp2a[pb][96+uu] + zp2b[pb][96+uu];
                c2 = fsig(zf)*c2 + fsig(zi)*ftanh(zg);
                h2v = fsig(zo)*ftanh(c2);
                #pragma unroll
                for (int r=0;r<4;r++) st_async_f32(dst[pb][r], h2v, rb[pb][r]);
                ys2row[(size_t)t*Hd + hh] = h2v;
            }
            if (tid == 160){   // release ys1[t] buffer to producer (all ranks)
                #pragma unroll
                for (int r=0;r<4;r++) mbar_arrive_remote(e1a[pb], (uint32_t)r);
            }
        }
        if (g2gate){
            out_state[(((size_t)1*Bn + b)*Hd + hh)*2 + 0] = h2v;
            out_state[(((size_t)1*Bn + b)*Hd + hh)*2 + 1] = c2;
        }
    }
    cluster_sync();   // no CTA exits while peers' st.async may target it
}

// ---------------- launcher ----------------
extern "C" void kernel_launch(void* const* d_in, const int* in_sizes, int n_in,
                              void* d_out, int out_size)
{
    const float* y1        = (const float*)d_in[0];
    const float* in_state2 = (const float*)d_in[1];
    const float* enc_w     = (const float*)d_in[2];
    const float* gamma     = (const float*)d_in[3];
    const float* beta      = (const float*)d_in[4];
    const float* Wih1      = (const float*)d_in[5];
    const float* Whh1      = (const float*)d_in[6];
    const float* bih1      = (const float*)d_in[7];
    const float* bhh1      = (const float*)d_in[8];
    const float* Wih2      = (const float*)d_in[9];
    const float* Whh2      = (const float*)d_in[10];
    const float* bih2      = (const float*)d_in[11];
    const float* bhh2      = (const float*)d_in[12];
    const float* Wd        = (const float*)d_in[13];
    const float* bd        = (const float*)d_in[14];
    const float* dec_w     = (const float*)d_in[15];
    float* out = (float*)d_out;

    void *encp, *zp, *ys2p, *w1gt, *wdt, *b1p, *meanp, *rstdp;
    cudaGetSymbolAddress(&encp,  g_enc);
    cudaGetSymbolAddress(&zp,    g_zpre);
    cudaGetSymbolAddress(&ys2p,  g_ys2);
    cudaGetSymbolAddress(&w1gt,  g_W1gT);
    cudaGetSymbolAddress(&wdt,   g_WdT);
    cudaGetSymbolAddress(&b1p,   g_bias1);
    cudaGetSymbolAddress(&meanp, g_mean);
    cudaGetSymbolAddress(&rstdp, g_rstd);

    prep_kernel<<<64,256>>>(enc_w,gamma,beta,Wih1,dec_w,Wd,bih1,bhh1,bih2,bhh2);
    enc_kernel<<<dim3(16,4,32),256>>>(y1);
    ln_kernel<<<(Bn*Td)/8,256>>>();
    gemm_kernel<<<dim3(500,8),256>>>((const float*)encp, (const float*)w1gt, (float*)zp,
                                     (const float*)b1p, (const float*)meanp, (const float*)rstdp,
                                     nullptr, 256, 512, 0);
    {
        float* outstate = out + (size_t)Bn*Fd*Td;
        lstm_kernel<<<Bn*4, 384>>>(in_state2, Whh1, Wih2, Whh2, outstate);
    }
    gemm_kernel<<<dim3(500,4),256>>>((const float*)ys2p, (const float*)wdt, (float*)zp,
                                     bd, nullptr, nullptr, (const float*)encp, 128, 256, 1);
    dec_kernel<<<dim3(16,8,32),256>>>((const float*)zp, out);
}

// round 13
// speedup vs baseline: 1.0724x; 1.0724x over previous
#include <cuda_runtime.h>
#include <cstdint>
#include <cstddef>

#define Bn 32
#define Fd 512
#define Td 2000
#define Ed 256
#define Hd 128
#define EPSf 1e-7f

// ---------------- static device scratch ----------------
__device__ float g_enc [ (size_t)Bn*Td*Ed ];
__device__ float g_zpre[ (size_t)Bn*Td*4*Hd ];   // reused as est
__device__ float g_ys2 [ (size_t)Bn*Td*Hd ];
__device__ float g_encwT[ Fd*Ed ];
__device__ float g_W1gT [ Ed*4*Hd ];
__device__ float g_decwT[ Ed*Fd ];
__device__ float g_WdT  [ Hd*Ed ];
__device__ float g_bias1[ 4*Hd ];
__device__ float g_bias2[ 4*Hd ];
__device__ float g_colsum[ 4*Hd ];    // S[j] = sum_e W1g[e][j]

typedef unsigned long long u64;

__device__ __forceinline__ float sigf(float x){ return 1.0f/(1.0f + expf(-x)); }
__device__ __forceinline__ float ftanh(float x){ float y; asm("tanh.approx.f32 %0, %1;" : "=f"(y) : "f"(x)); return y; }
__device__ __forceinline__ float fsig(float x){ return fmaf(ftanh(0.5f*x), 0.5f, 0.5f); }

__device__ __forceinline__ void ffma2(u64& d, u64 a, u64 b){
    asm("fma.rn.f32x2 %0, %1, %2, %0;" : "+l"(d) : "l"(a), "l"(b));
}
__device__ __forceinline__ u64 packdup(float a){
    u64 r; asm("mov.b64 %0, {%1, %1};" : "=l"(r) : "f"(a)); return r;
}
__device__ __forceinline__ void unpk(float& lo, float& hi, u64 v){
    asm("mov.b64 {%0, %1}, %2;" : "=f"(lo), "=f"(hi) : "l"(v));
}
__device__ __forceinline__ float upsum(u64 a, u64 b){
    float x,y,z,w; unpk(x,y,a); unpk(z,w,b); return (x+y)+(z+w);
}

__device__ __forceinline__ uint32_t smem_u32(const void* p){ return (uint32_t)__cvta_generic_to_shared(p); }
__device__ __forceinline__ uint32_t mapa_rank(uint32_t laddr, uint32_t r){
    uint32_t ra; asm("mapa.shared::cluster.u32 %0, %1, %2;" : "=r"(ra) : "r"(laddr), "r"(r)); return ra;
}
__device__ __forceinline__ void st_async_f32(uint32_t dst, float v, uint32_t rbar){
    asm volatile("st.async.shared::cluster.mbarrier::complete_tx::bytes.f32 [%0], %1, [%2];"
                 :: "r"(dst), "f"(v), "r"(rbar) : "memory");
}
__device__ __forceinline__ void mbar_init(uint32_t a, uint32_t cnt){
    asm volatile("mbarrier.init.shared.b64 [%0], %1;" :: "r"(a), "r"(cnt) : "memory");
}
__device__ __forceinline__ void mbar_arrive_expect(uint32_t a, uint32_t bytes){
    asm volatile("mbarrier.arrive.expect_tx.shared.b64 _, [%0], %1;" :: "r"(a), "r"(bytes) : "memory");
}
__device__ __forceinline__ void mbar_wait(uint32_t a, int ph){
    asm volatile(
        "{\n\t.reg .pred P;\n\t"
        "WL_%=:\n\t"
        "mbarrier.try_wait.parity.acquire.cluster.shared::cta.b64 P, [%0], %1, 0x989680;\n\t"
        "@P bra.uni WD_%=;\n\t"
        "bra.uni WL_%=;\n\t"
        "WD_%=:\n\t}"
        :: "r"(a), "r"((uint32_t)ph) : "memory");
}
__device__ __forceinline__ void cluster_sync(){
    asm volatile("barrier.cluster.arrive.aligned;" ::: "memory");
    asm volatile("barrier.cluster.wait.aligned;" ::: "memory");
}
__device__ __forceinline__ void bar_sync_1_256(){
    asm volatile("bar.sync 1, 256;" ::: "memory");
}

// ---------------- prep ----------------
__global__ void prep_kernel(const float* __restrict__ enc_w, const float* __restrict__ gamma,
                            const float* __restrict__ beta,  const float* __restrict__ Wih1,
                            const float* __restrict__ dec_w, const float* __restrict__ Wd,
                            const float* __restrict__ bih1,  const float* __restrict__ bhh1,
                            const float* __restrict__ bih2,  const float* __restrict__ bhh2)
{
    int i = blockIdx.x*blockDim.x + threadIdx.x;
    int n = gridDim.x*blockDim.x;
    for (int idx=i; idx<Fd*Ed; idx+=n){ int f=idx/Ed, e=idx%Ed; g_encwT[idx] = enc_w[e*Fd + f]; }
    for (int idx=i; idx<Ed*4*Hd; idx+=n){ int e=idx>>9, j=idx&511; g_W1gT[idx] = Wih1[j*Ed + e]*gamma[e]; }
    for (int idx=i; idx<Ed*Fd; idx+=n){ int e=idx>>9, f=idx&511; g_decwT[idx] = dec_w[f*Ed + e]; }
    for (int idx=i; idx<Hd*Ed; idx+=n){ int h=idx>>8, e=idx&255; g_WdT[idx] = Wd[e*Hd + h]; }
    for (int j=i; j<4*Hd; j+=n) g_bias2[j] = bih2[j] + bhh2[j];
    int wid = i >> 5, lane = i & 31;
    for (int j=wid; j<4*Hd; j += n>>5){
        float s = 0.f, cs = 0.f;
        for (int e=lane; e<Ed; e+=32){
            float w = Wih1[j*Ed + e];
            s  += beta[e]*w;
            cs += gamma[e]*w;
        }
        #pragma unroll
        for (int o=16;o>0;o>>=1){
            s  += __shfl_xor_sync(0xffffffffu, s, o);
            cs += __shfl_xor_sync(0xffffffffu, cs, o);
        }
        if (lane==0){
            g_bias1[j]  = s + bih1[j] + bhh1[j];
            g_colsum[j] = cs;
        }
    }
}

// ---------------- enc GEMM (R7 proven) ----------------
__global__ void __launch_bounds__(256) enc_kernel(const float* __restrict__ y1)
{
    __shared__ __align__(16) float As[2][16][128];
    __shared__ __align__(16) float Bs[2][16][64];
    const int b = blockIdx.z;
    const int t0 = blockIdx.x*128, e0 = blockIdx.y*64;
    const int tid = threadIdx.x;
    const int lk = tid>>4, lt = (tid&15)*8;
    const int bk = tid>>4, bn = (tid&15)*4;
    const int ty = tid>>4, tx = tid&15;
    const float* yb = y1 + (size_t)b*Fd*Td;
    u64 acc[8][2] = {};
    float4 ra0, ra1, rb0;
    {
        int t = t0 + lt;
        ra0 = make_float4(0.f,0.f,0.f,0.f); ra1 = ra0;
        if (t   < Td) ra0 = *(const float4*)(yb + (size_t)lk*Td + t);
        if (t+4 < Td) ra1 = *(const float4*)(yb + (size_t)lk*Td + t + 4);
        rb0 = *(const float4*)(g_encwT + (size_t)bk*Ed + e0 + bn);
        *(float4*)&As[0][lk][lt]   = ra0;
        *(float4*)&As[0][lk][lt+4] = ra1;
        *(float4*)&Bs[0][bk][bn]   = rb0;
    }
    __syncthreads();
    int cur = 0;
    for (int k0=0;k0<Fd;k0+=16){
        const bool more = (k0+16 < Fd);
        if (more){
            int k = k0 + 16 + lk;
            int t = t0 + lt;
            ra0 = make_float4(0.f,0.f,0.f,0.f); ra1 = ra0;
            if (t   < Td) ra0 = *(const float4*)(yb + (size_t)k*Td + t);
            if (t+4 < Td) ra1 = *(const float4*)(yb + (size_t)k*Td + t + 4);
            rb0 = *(const float4*)(g_encwT + (size_t)(k0+16+bk)*Ed + e0 + bn);
        }
        #pragma unroll
        for (int kk=0;kk<16;kk++){
            ulonglong2 bp = *(const ulonglong2*)&Bs[cur][kk][tx*4];
            float4 a0 = *(const float4*)&As[cur][kk][ty*8];
            float4 a1 = *(const float4*)&As[cur][kk][ty*8+4];
            u64 d0=packdup(a0.x), d1=packdup(a0.y), d2=packdup(a0.z), d3=packdup(a0.w);
            u64 d4=packdup(a1.x), d5=packdup(a1.y), d6=packdup(a1.z), d7=packdup(a1.w);
            ffma2(acc[0][0],d0,bp.x); ffma2(acc[0][1],d0,bp.y);
            ffma2(acc[1][0],d1,bp.x); ffma2(acc[1][1],d1,bp.y);
            ffma2(acc[2][0],d2,bp.x); ffma2(acc[2][1],d2,bp.y);
            ffma2(acc[3][0],d3,bp.x); ffma2(acc[3][1],d3,bp.y);
            ffma2(acc[4][0],d4,bp.x); ffma2(acc[4][1],d4,bp.y);
            ffma2(acc[5][0],d5,bp.x); ffma2(acc[5][1],d5,bp.y);
            ffma2(acc[6][0],d6,bp.x); ffma2(acc[6][1],d6,bp.y);
            ffma2(acc[7][0],d7,bp.x); ffma2(acc[7][1],d7,bp.y);
        }
        if (more){
            int nb = cur^1;
            *(float4*)&As[nb][lk][lt]   = ra0;
            *(float4*)&As[nb][lk][lt+4] = ra1;
            *(float4*)&Bs[nb][bk][bn]   = rb0;
        }
        __syncthreads();
        cur ^= 1;
    }
    #pragma unroll
    for (int i=0;i<8;i++){
        int t = t0 + ty*8 + i;
        if (t < Td){
            float4 v;
            unpk(v.x, v.y, acc[i][0]);
            unpk(v.z, v.w, acc[i][1]);
            *(float4*)(g_enc + ((size_t)b*Td + t)*Ed + e0 + tx*4) = v;
        }
    }
}

// ---------------- GEMM modes 0/1: 128(m) x 64(n), [k][m] A tile ----------------
// mode 0: fused layernorm — raw GEMM + in-flight row stats, normalize at store:
//   out = rs*(G - mu*S[j]) + b1[j]
// mode 1: out = sigmoid(acc + bias) * enc
__global__ void __launch_bounds__(256) gemm_kernel(
    const float* __restrict__ A, const float* __restrict__ Bm, float* __restrict__ C,
    const float* __restrict__ bias, const float* __restrict__ colsum,
    const float* __restrict__ encp, int K, int N, int mode)
{
    __shared__ __align__(16) float As[2][16][128];
    __shared__ __align__(16) float Bs[2][16][64];
    const int tid = threadIdx.x;
    const int m0 = blockIdx.x*128, n0 = blockIdx.y*64;
    const int ar = tid>>1, ak = (tid&1)*8;
    const int bk = tid>>4, bn = (tid&15)*4;
    const int ty = tid>>4, tx = tid&15;
    const float* Arow = A + (size_t)(m0+ar)*K;
    u64 acc[8][2] = {};
    float ssum = 0.f, sqsum = 0.f;
    float4 ra0, ra1, rb0;
    {
        ra0 = *(const float4*)(Arow + ak);
        ra1 = *(const float4*)(Arow + ak + 4);
        if (mode==0){
            ssum  += (ra0.x+ra0.y)+(ra0.z+ra0.w) + (ra1.x+ra1.y)+(ra1.z+ra1.w);
            sqsum += ra0.x*ra0.x+ra0.y*ra0.y+ra0.z*ra0.z+ra0.w*ra0.w
                   + ra1.x*ra1.x+ra1.y*ra1.y+ra1.z*ra1.z+ra1.w*ra1.w;
        }
        rb0 = *(const float4*)(Bm + (size_t)bk*N + n0 + bn);
        As[0][ak+0][ar]=ra0.x; As[0][ak+1][ar]=ra0.y; As[0][ak+2][ar]=ra0.z; As[0][ak+3][ar]=ra0.w;
        As[0][ak+4][ar]=ra1.x; As[0][ak+5][ar]=ra1.y; As[0][ak+6][ar]=ra1.z; As[0][ak+7][ar]=ra1.w;
        *(float4*)&Bs[0][bk][bn] = rb0;
    }
    __syncthreads();
    int cur = 0;
    for (int k0=0;k0<K;k0+=16){
        const bool more = (k0+16 < K);
        if (more){
            ra0 = *(const float4*)(Arow + k0+16 + ak);
            ra1 = *(const float4*)(Arow + k0+16 + ak + 4);
            if (mode==0){
                ssum  += (ra0.x+ra0.y)+(ra0.z+ra0.w) + (ra1.x+ra1.y)+(ra1.z+ra1.w);
                sqsum += ra0.x*ra0.x+ra0.y*ra0.y+ra0.z*ra0.z+ra0.w*ra0.w
                       + ra1.x*ra1.x+ra1.y*ra1.y+ra1.z*ra1.z+ra1.w*ra1.w;
            }
            rb0 = *(const float4*)(Bm + (size_t)(k0+16+bk)*N + n0 + bn);
        }
        #pragma unroll
        for (int kk=0;kk<16;kk++){
            ulonglong2 bp = *(const ulonglong2*)&Bs[cur][kk][tx*4];
            float4 a0 = *(const float4*)&As[cur][kk][ty*8];
            float4 a1 = *(const float4*)&As[cur][kk][ty*8+4];
            u64 d0=packdup(a0.x), d1=packdup(a0.y), d2=packdup(a0.z), d3=packdup(a0.w);
            u64 d4=packdup(a1.x), d5=packdup(a1.y), d6=packdup(a1.z), d7=packdup(a1.w);
            ffma2(acc[0][0],d0,bp.x); ffma2(acc[0][1],d0,bp.y);
            ffma2(acc[1][0],d1,bp.x); ffma2(acc[1][1],d1,bp.y);
            ffma2(acc[2][0],d2,bp.x); ffma2(acc[2][1],d2,bp.y);
            ffma2(acc[3][0],d3,bp.x); ffma2(acc[3][1],d3,bp.y);
            ffma2(acc[4][0],d4,bp.x); ffma2(acc[4][1],d4,bp.y);
            ffma2(acc[5][0],d5,bp.x); ffma2(acc[5][1],d5,bp.y);
            ffma2(acc[6][0],d6,bp.x); ffma2(acc[6][1],d6,bp.y);
            ffma2(acc[7][0],d7,bp.x); ffma2(acc[7][1],d7,bp.y);
        }
        if (more){
            int nb = cur^1;
            As[nb][ak+0][ar]=ra0.x; As[nb][ak+1][ar]=ra0.y; As[nb][ak+2][ar]=ra0.z; As[nb][ak+3][ar]=ra0.w;
            As[nb][ak+4][ar]=ra1.x; As[nb][ak+5][ar]=ra1.y; As[nb][ak+6][ar]=ra1.z; As[nb][ak+7][ar]=ra1.w;
            *(float4*)&Bs[nb][bk][bn] = rb0;
        }
        __syncthreads();
        cur ^= 1;
    }
    if (mode==0){
        // combine the two threads of this row (tid pairs share ar): lane^1
        float mu, rs;
        {
            float s2 = ssum  + __shfl_xor_sync(0xffffffffu, ssum, 1);
            float q2 = sqsum + __shfl_xor_sync(0xffffffffu, sqsum, 1);
            mu = s2 * (1.0f/256.0f);
            rs = rsqrtf(fmaf(-mu, mu, q2*(1.0f/256.0f)) + EPSf);
        }
        // each thread stores its 8 output rows: rows m0+ty*8+i — but stats are per
        // source row ar. Rows in the store phase differ from ar, so exchange via smem.
        __shared__ float smu[128], srs[128];
        if ((tid&1)==0){ smu[ar] = mu; srs[ar] = rs; }
        __syncthreads();
        float4 bv = *(const float4*)(bias + n0 + tx*4);
        float4 sv = *(const float4*)(colsum + n0 + tx*4);
        #pragma unroll
        for (int i=0;i<8;i++){
            int mrow = ty*8 + i;
            float rmu = smu[mrow], rrs = srs[mrow];
            float4 v;
            unpk(v.x, v.y, acc[i][0]);
            unpk(v.z, v.w, acc[i][1]);
            v.x = fmaf(rrs, v.x - rmu*sv.x, bv.x);
            v.y = fmaf(rrs, v.y - rmu*sv.y, bv.y);
            v.z = fmaf(rrs, v.z - rmu*sv.z, bv.z);
            v.w = fmaf(rrs, v.w - rmu*sv.w, bv.w);
            *(float4*)(C + (size_t)(m0+mrow)*N + n0 + tx*4) = v;
        }
    } else {
        float4 bv = make_float4(0.f,0.f,0.f,0.f);
        if (bias) bv = *(const float4*)(bias + n0 + tx*4);
        #pragma unroll
        for (int i=0;i<8;i++){
            int m = m0 + ty*8 + i;
            float4 v;
            unpk(v.x, v.y, acc[i][0]);
            unpk(v.z, v.w, acc[i][1]);
            v.x += bv.x; v.y += bv.y; v.z += bv.z; v.w += bv.w;
            if (mode==1){
                float4 e = *(const float4*)(encp + (size_t)m*N + n0 + tx*4);
                v.x = sigf(v.x)*e.x; v.y = sigf(v.y)*e.y; v.z = sigf(v.z)*e.z; v.w = sigf(v.w)*e.w;
            }
            *(float4*)(C + (size_t)m*N + n0 + tx*4) = v;
        }
    }
}

// ---------------- decode GEMM (R7 proven) ----------------
__global__ void __launch_bounds__(256) dec_kernel(const float* __restrict__ A, float* __restrict__ C)
{
    __shared__ float buf[8256];
    float* AsB = buf;
    float* BsB = buf + 4096;
    const int b  = blockIdx.z;
    const int m0 = blockIdx.x*128;
    const int n0 = blockIdx.y*64;
    const int tid = threadIdx.x;
    const int ar = tid>>1, ak = (tid&1)*8;
    const int bk = tid>>4, bn = (tid&15)*4;
    const int ty = tid>>4, tx = tid&15;
    const float* Arow = A + ((size_t)b*Td + m0 + ar)*Ed;
    u64 acc[8][2] = {};
    float4 ra0, ra1, rb0;
    {
        ra0 = *(const float4*)(Arow + ak);
        ra1 = *(const float4*)(Arow + ak + 4);
        rb0 = *(const float4*)(g_decwT + (size_t)bk*Fd + n0 + bn);
        AsB[(ak+0)*128+ar]=ra0.x; AsB[(ak+1)*128+ar]=ra0.y; AsB[(ak+2)*128+ar]=ra0.z; AsB[(ak+3)*128+ar]=ra0.w;
        AsB[(ak+4)*128+ar]=ra1.x; AsB[(ak+5)*128+ar]=ra1.y; AsB[(ak+6)*128+ar]=ra1.z; AsB[(ak+7)*128+ar]=ra1.w;
        *(float4*)&BsB[bk*64 + bn] = rb0;
    }
    __syncthreads();
    int cur = 0;
    for (int k0=0;k0<Ed;k0+=16){
        const bool more = (k0+16 < Ed);
        if (more){
            ra0 = *(const float4*)(Arow + k0+16 + ak);
            ra1 = *(const float4*)(Arow + k0+16 + ak + 4);
            rb0 = *(const float4*)(g_decwT + (size_t)(k0+16+bk)*Fd + n0 + bn);
        }
        const float* asb = &AsB[cur*2048];
        const float* bsb = &BsB[cur*1024];
        #pragma unroll
        for (int kk=0;kk<16;kk++){
            ulonglong2 bp = *(const ulonglong2*)&bsb[kk*64 + tx*4];
            float4 a0 = *(const float4*)&asb[kk*128 + ty*8];
            float4 a1 = *(const float4*)&asb[kk*128 + ty*8 + 4];
            u64 d0=packdup(a0.x), d1=packdup(a0.y), d2=packdup(a0.z), d3=packdup(a0.w);
            u64 d4=packdup(a1.x), d5=packdup(a1.y), d6=packdup(a1.z), d7=packdup(a1.w);
            ffma2(acc[0][0],d0,bp.x); ffma2(acc[0][1],d0,bp.y);
            ffma2(acc[1][0],d1,bp.x); ffma2(acc[1][1],d1,bp.y);
            ffma2(acc[2][0],d2,bp.x); ffma2(acc[2][1],d2,bp.y);
            ffma2(acc[3][0],d3,bp.x); ffma2(acc[3][1],d3,bp.y);
            ffma2(acc[4][0],d4,bp.x); ffma2(acc[4][1],d4,bp.y);
            ffma2(acc[5][0],d5,bp.x); ffma2(acc[5][1],d5,bp.y);
            ffma2(acc[6][0],d6,bp.x); ffma2(acc[6][1],d6,bp.y);
            ffma2(acc[7][0],d7,bp.x); ffma2(acc[7][1],d7,bp.y);
        }
        if (more){
            int nb = cur^1;
            float* ap = &AsB[nb*2048];
            ap[(ak+0)*128+ar]=ra0.x; ap[(ak+1)*128+ar]=ra0.y; ap[(ak+2)*128+ar]=ra0.z; ap[(ak+3)*128+ar]=ra0.w;
            ap[(ak+4)*128+ar]=ra1.x; ap[(ak+5)*128+ar]=ra1.y; ap[(ak+6)*128+ar]=ra1.z; ap[(ak+7)*128+ar]=ra1.w;
            *(float4*)&BsB[nb*1024 + bk*64 + bn] = rb0;
        }
        __syncthreads();
        cur ^= 1;
    }
    __syncthreads();
    #pragma unroll
    for (int i=0;i<8;i++){
        float v0,v1,v2,v3;
        unpk(v0,v1,acc[i][0]); unpk(v2,v3,acc[i][1]);
        int ml = ty*8 + i;
        buf[(tx*4+0)*129 + ml] = v0;
        buf[(tx*4+1)*129 + ml] = v1;
        buf[(tx*4+2)*129 + ml] = v2;
        buf[(tx*4+3)*129 + ml] = v3;
    }
    __syncthreads();
    {
        int f = tid>>2;
        int seg = (tid&3)*32;
        float* crow = C + ((size_t)b*Fd + n0 + f)*Td;
        const float* trow = &buf[f*129 + seg];
        #pragma unroll
        for (int q=0;q<8;q++){
            int t = m0 + seg + q*4;
            if (t < Td){
                float4 v = make_float4(trow[q*4+0], trow[q*4+1], trow[q*4+2], trow[q*4+3]);
                *(float4*)(crow + t) = v;
            }
        }
    }
}

// ---------------- LSTM scan (R9 proven: phase-split, early h1 broadcast) ----------------
__global__ void __launch_bounds__(384,1) __cluster_dims__(4,1,1)
lstm_kernel(const float* __restrict__ in_state2,
            const float* __restrict__ Whh1, const float* __restrict__ Wih2,
            const float* __restrict__ Whh2, float* __restrict__ out_state)
{
    __shared__ __align__(16) u64   mbH1[2], mbH2[2];
    __shared__ __align__(16) float h1b[2][128];
    __shared__ __align__(16) float h2b[2][128];
    __shared__ __align__(16) float h1loc[128];
    __shared__ __align__(16) float zp1[2][128];
    __shared__ __align__(16) float zp2[2][3][128];

    const int tid  = threadIdx.x;
    const int rank = blockIdx.x & 3, b = blockIdx.x >> 2;
    const int tau  = tid >> 7, row = tid & 127;
    const int gate = row >> 5, u = row & 31;
    const int Rg = gate*128 + rank*32 + u;

    const uint32_t mh1_0 = smem_u32(&mbH1[0]);
    const uint32_t mh1_1 = smem_u32(&mbH1[1]);
    const uint32_t mh2_0 = smem_u32(&mbH2[0]);
    const uint32_t mh2_1 = smem_u32(&mbH2[1]);

    if (tid == 0){
        mbar_init(mh1_0, 1); mbar_init(mh1_1, 1);
        mbar_init(mh2_0, 1); mbar_init(mh2_1, 1);
        mbar_arrive_expect(mh1_0, 512);
        mbar_arrive_expect(mh1_1, 512);
        mbar_arrive_expect(mh2_0, 512);
        mbar_arrive_expect(mh2_1, 512);
    }

    u64 Ar[32], Br[32];
    {
        const float *pA, *pB;
        if (tau == 0){ pA = Whh1 + (size_t)Rg*Hd;      pB = Wih2 + (size_t)Rg*Hd; }
        else if (tau == 1){ pA = Whh1 + (size_t)Rg*Hd + 64; pB = Wih2 + (size_t)Rg*Hd + 64; }
        else { pA = Whh2 + (size_t)Rg*Hd;              pB = Whh2 + (size_t)Rg*Hd + 64; }
        const u64* qa = (const u64*)pA;
        const u64* qb = (const u64*)pB;
        #pragma unroll
        for (int k=0;k<32;k++){ Ar[k] = qa[k]; Br[k] = qb[k]; }
    }
    if (tau == 0){
        h1b[1][row] = in_state2[(((size_t)0*Bn + b)*Hd + row)*2 + 0];
        h2b[0][row] = in_state2[(((size_t)1*Bn + b)*Hd + row)*2 + 0];
    }
    const float b2r = g_bias2[Rg];

    float c1=0.f, c2=0.f, h1v=0.f, h2v=0.f;
    int hh = 0;
    const bool is_l2 = (tid < 32), is_l1 = (tid >= 32 && tid < 64);
    uint32_t dstA[2][4], rbA[2][4];
    if (is_l2 || is_l1){
        int uu = is_l2 ? tid : (tid-32);
        hh = rank*32 + uu;
        uint32_t la_h = is_l2 ? smem_u32(&h2b[0][hh]) : smem_u32(&h1b[0][hh]);
        #pragma unroll
        for (int s=0;s<2;s++){
            uint32_t mbs = is_l2 ? (s ? mh2_1 : mh2_0) : (s ? mh1_1 : mh1_0);
            #pragma unroll
            for (int r=0;r<4;r++){
                dstA[s][r] = mapa_rank(la_h + s*512, (uint32_t)r);
                rbA[s][r]  = mapa_rank(mbs, (uint32_t)r);
            }
        }
        if (is_l2) c2 = in_state2[(((size_t)1*Bn + b)*Hd + hh)*2 + 1];
        else       c1 = in_state2[(((size_t)0*Bn + b)*Hd + hh)*2 + 1];
    }
    __syncthreads();
    cluster_sync();

    const float* zrow = g_zpre + (size_t)b*Td*512 + Rg;
    float* ys2row = g_ys2 + (size_t)b*Td*Hd;
    float zp_cur = 0.f;
    if (tau == 0) zp_cur = zrow[512];

    // ---- prologue: h1[0] from h1b[1] ----
    if (tau < 2){
        float zp0 = (tau==0) ? zrow[0] : 0.f;
        const ulonglong2* xa = (const ulonglong2*)&h1b[1][tau*64];
        u64 a1 = 0, a2 = 0;
        #pragma unroll
        for (int k=0;k<16;k++){
            ulonglong2 x = xa[k];
            ffma2(a1, Ar[2*k],   x.x);
            ffma2(a2, Ar[2*k+1], x.y);
        }
        zp1[tau][row] = upsum(a1, a2) + zp0;
        bar_sync_1_256();
        if (is_l1){
            int uu = tid-32;
            float zi = zp1[0][uu], zf = zp1[0][32+uu];
            float zg = zp1[0][64+uu], zo = zp1[0][96+uu];
            zi += zp1[1][uu]; zf += zp1[1][32+uu]; zg += zp1[1][64+uu]; zo += zp1[1][96+uu];
            c1 = fsig(zf)*c1 + fsig(zi)*ftanh(zg);
            h1v = fsig(zo)*ftanh(c1);
            #pragma unroll
            for (int r=0;r<4;r++) st_async_f32(dstA[0][r], h1v, rbA[0][r]);
        }
    }
    int phH1[2] = {0,0}, phH2[2] = {0,0};
    if (tid < 256){
        mbar_wait(mh1_0, 0); phH1[0] = 1;
        if (tid == 128) mbar_arrive_expect(mh1_0, 512);
    }

    // ---- main loop ----
    for (int t=0; t<Td; t++){
        const int p = t & 1, q = p ^ 1;
        float zp_next = 0.f;
        if (tau == 0){
            int tn = t + 2; if (tn > Td-1) tn = Td-1;
            zp_next = __ldg(zrow + (size_t)tn*512);
        }

        if (tau < 2){
            if (tid < 32){
                *(float4*)&h1loc[tid*4] = *(const float4*)&h1b[p][tid*4];
            }
            const ulonglong2* xa = (const ulonglong2*)&h1b[p][tau*64];
            u64 a1=0, a2=0;
            #pragma unroll
            for (int k=0;k<16;k++){
                ulonglong2 x = xa[k];
                ffma2(a1, Ar[2*k],   x.x);
                ffma2(a2, Ar[2*k+1], x.y);
            }
            zp1[tau][row] = upsum(a1, a2) + ((tau==0) ? zp_cur : 0.f);
            bar_sync_1_256();
            if (is_l1){
                int uu = tid-32;
                float zi = zp1[0][uu]    + zp1[1][uu];
                float zf = zp1[0][32+uu] + zp1[1][32+uu];
                float zg = zp1[0][64+uu] + zp1[1][64+uu];
                float zo = zp1[0][96+uu] + zp1[1][96+uu];
                if (t < Td-1){
                    c1 = fsig(zf)*c1 + fsig(zi)*ftanh(zg);
                    h1v = fsig(zo)*ftanh(c1);
                }
                #pragma unroll
                for (int r=0;r<4;r++) st_async_f32(dstA[q][r], h1v, rbA[q][r]);
            }
            {
                const ulonglong2* xb = (const ulonglong2*)&h1loc[tau*64];
                u64 b1=0, b2a=0;
                #pragma unroll
                for (int k=0;k<16;k++){
                    ulonglong2 x = xb[k];
                    ffma2(b1,  Br[2*k],   x.x);
                    ffma2(b2a, Br[2*k+1], x.y);
                }
                zp2[p][tau][row] = upsum(b1, b2a);
            }
        } else {
            const ulonglong2* xa = (const ulonglong2*)&h2b[p][0];
            const ulonglong2* xb = (const ulonglong2*)&h2b[p][64];
            u64 a1=0, a2=0, b1=0, b2a=0;
            #pragma unroll
            for (int k=0;k<16;k++){
                ulonglong2 x = xa[k], y = xb[k];
                ffma2(a1,  Ar[2*k],   x.x);
                ffma2(a2,  Ar[2*k+1], x.y);
                ffma2(b1,  Br[2*k],   y.x);
                ffma2(b2a, Br[2*k+1], y.y);
            }
            zp2[p][2][row] = upsum(a1, a2) + upsum(b1, b2a) + b2r;
        }
        __syncthreads();

        if (is_l2){
            float zi = zp2[p][0][u]    + zp2[p][1][u]    + zp2[p][2][u];
            float zf = zp2[p][0][32+u] + zp2[p][1][32+u] + zp2[p][2][32+u];
            float zg = zp2[p][0][64+u] + zp2[p][1][64+u] + zp2[p][2][64+u];
            float zo = zp2[p][0][96+u] + zp2[p][1][96+u] + zp2[p][2][96+u];
            c2 = fsig(zf)*c2 + fsig(zi)*ftanh(zg);
            h2v = fsig(zo)*ftanh(c2);
            #pragma unroll
            for (int r=0;r<4;r++) st_async_f32(dstA[q][r], h2v, rbA[q][r]);
            ys2row[(size_t)t*Hd + hh] = h2v;
        }

        if (tid < 256){
            uint32_t mb = q ? mh1_1 : mh1_0;
            mbar_wait(mb, phH1[q]); phH1[q] ^= 1;
            if (tid == 128) mbar_arrive_expect(mb, 512);
        } else {
            uint32_t mb = q ? mh2_1 : mh2_0;
            mbar_wait(mb, phH2[q]); phH2[q] ^= 1;
            if (tid == 256) mbar_arrive_expect(mb, 512);
        }
        zp_cur = zp_next;
    }

    if (is_l2){
        out_state[(((size_t)1*Bn + b)*Hd + hh)*2 + 0] = h2v;
        out_state[(((size_t)1*Bn + b)*Hd + hh)*2 + 1] = c2;
    } else if (is_l1){
        out_state[(((size_t)0*Bn + b)*Hd + hh)*2 + 0] = h1v;
        out_state[(((size_t)0*Bn + b)*Hd + hh)*2 + 1] = c1;
    }
}

// ---------------- launcher ----------------
extern "C" void kernel_launch(void* const* d_in, const int* in_sizes, int n_in,
                              void* d_out, int out_size)
{
    const float* y1        = (const float*)d_in[0];
    const float* in_state2 = (const float*)d_in[1];
    const float* enc_w     = (const float*)d_in[2];
    const float* gamma     = (const float*)d_in[3];
    const float* beta      = (const float*)d_in[4];
    const float* Wih1      = (const float*)d_in[5];
    const float* Whh1      = (const float*)d_in[6];
    const float* bih1      = (const float*)d_in[7];
    const float* bhh1      = (const float*)d_in[8];
    const float* Wih2      = (const float*)d_in[9];
    const float* Whh2      = (const float*)d_in[10];
    const float* bih2      = (const float*)d_in[11];
    const float* bhh2      = (const float*)d_in[12];
    const float* Wd        = (const float*)d_in[13];
    const float* bd        = (const float*)d_in[14];
    const float* dec_w     = (const float*)d_in[15];
    float* out = (float*)d_out;

    void *encp, *zp, *ys2p, *w1gt, *wdt, *b1p, *csp;
    cudaGetSymbolAddress(&encp,  g_enc);
    cudaGetSymbolAddress(&zp,    g_zpre);
    cudaGetSymbolAddress(&ys2p,  g_ys2);
    cudaGetSymbolAddress(&w1gt,  g_W1gT);
    cudaGetSymbolAddress(&wdt,   g_WdT);
    cudaGetSymbolAddress(&b1p,   g_bias1);
    cudaGetSymbolAddress(&csp,   g_colsum);

    prep_kernel<<<64,256>>>(enc_w,gamma,beta,Wih1,dec_w,Wd,bih1,bhh1,bih2,bhh2);
    enc_kernel<<<dim3(16,4,32),256>>>(y1);
    // zpre1 with fused layernorm: M=64000, N=512, K=256
    gemm_kernel<<<dim3(500,8),256>>>((const float*)encp, (const float*)w1gt, (float*)zp,
                                     (const float*)b1p, (const float*)csp,
                                     nullptr, 256, 512, 0);
    {
        float* outstate = out + (size_t)Bn*Fd*Td;
        lstm_kernel<<<Bn*4, 384>>>(in_state2, Whh1, Wih2, Whh2, outstate);
    }
    // est: M=64000, N=256, K=128
    gemm_kernel<<<dim3(500,4),256>>>((const float*)ys2p, (const float*)wdt, (float*)zp,
                                     bd, nullptr, (const float*)encp, 128, 256, 1);
    dec_kernel<<<dim3(16,8,32),256>>>((const float*)zp, out);
}

// round 14
// speedup vs baseline: 1.1150x; 1.0398x over previous
#include <cuda_runtime.h>
#include <cstdint>
#include <cstddef>

#define Bn 32
#define Fd 512
#define Td 2000
#define Ed 256
#define Hd 128
#define EPSf 1e-7f

// ---------------- static device scratch ----------------
__device__ float g_enc [ (size_t)Bn*Td*Ed ];
__device__ float g_zpre[ (size_t)Bn*Td*4*Hd ];   // reused as est
__device__ float g_ys2 [ (size_t)Bn*Td*Hd ];
__device__ float g_encwT[ Fd*Ed ];
__device__ float g_W1gT [ Ed*4*Hd ];
__device__ float g_decwT[ Ed*Fd ];
__device__ float g_WdT  [ Hd*Ed ];
__device__ float g_bias1[ 4*Hd ];
__device__ float g_bias2[ 4*Hd ];
__device__ float g_colsum[ 4*Hd ];

typedef unsigned long long u64;

__device__ __forceinline__ float sigf(float x){ return 1.0f/(1.0f + expf(-x)); }
__device__ __forceinline__ float ftanh(float x){ float y; asm("tanh.approx.f32 %0, %1;" : "=f"(y) : "f"(x)); return y; }
__device__ __forceinline__ float fsig(float x){ return fmaf(ftanh(0.5f*x), 0.5f, 0.5f); }

__device__ __forceinline__ void ffma2(u64& d, u64 a, u64 b){
    asm("fma.rn.f32x2 %0, %1, %2, %0;" : "+l"(d) : "l"(a), "l"(b));
}
__device__ __forceinline__ u64 packdup(float a){
    u64 r; asm("mov.b64 %0, {%1, %1};" : "=l"(r) : "f"(a)); return r;
}
__device__ __forceinline__ void unpk(float& lo, float& hi, u64 v){
    asm("mov.b64 {%0, %1}, %2;" : "=f"(lo), "=f"(hi) : "l"(v));
}
__device__ __forceinline__ float upsum(u64 a, u64 b){
    float x,y,z,w; unpk(x,y,a); unpk(z,w,b); return (x+y)+(z+w);
}

__device__ __forceinline__ uint32_t smem_u32(const void* p){ return (uint32_t)__cvta_generic_to_shared(p); }
__device__ __forceinline__ uint32_t mapa_rank(uint32_t laddr, uint32_t r){
    uint32_t ra; asm("mapa.shared::cluster.u32 %0, %1, %2;" : "=r"(ra) : "r"(laddr), "r"(r)); return ra;
}
__device__ __forceinline__ void st_async_f32(uint32_t dst, float v, uint32_t rbar){
    asm volatile("st.async.shared::cluster.mbarrier::complete_tx::bytes.f32 [%0], %1, [%2];"
                 :: "r"(dst), "f"(v), "r"(rbar) : "memory");
}
__device__ __forceinline__ void mbar_init(uint32_t a, uint32_t cnt){
    asm volatile("mbarrier.init.shared.b64 [%0], %1;" :: "r"(a), "r"(cnt) : "memory");
}
__device__ __forceinline__ void mbar_arrive_expect(uint32_t a, uint32_t bytes){
    asm volatile("mbarrier.arrive.expect_tx.shared.b64 _, [%0], %1;" :: "r"(a), "r"(bytes) : "memory");
}
__device__ __forceinline__ void mbar_wait(uint32_t a, int ph){
    asm volatile(
        "{\n\t.reg .pred P;\n\t"
        "WL_%=:\n\t"
        "mbarrier.try_wait.parity.acquire.cluster.shared::cta.b64 P, [%0], %1, 0x989680;\n\t"
        "@P bra.uni WD_%=;\n\t"
        "bra.uni WL_%=;\n\t"
        "WD_%=:\n\t}"
        :: "r"(a), "r"((uint32_t)ph) : "memory");
}
__device__ __forceinline__ void cluster_sync(){
    asm volatile("barrier.cluster.arrive.aligned;" ::: "memory");
    asm volatile("barrier.cluster.wait.aligned;" ::: "memory");
}
__device__ __forceinline__ void bar_sync_1_256(){
    asm volatile("bar.sync 1, 256;" ::: "memory");
}

// ---------------- prep ----------------
__global__ void prep_kernel(const float* __restrict__ enc_w, const float* __restrict__ gamma,
                            const float* __restrict__ beta,  const float* __restrict__ Wih1,
                            const float* __restrict__ dec_w, const float* __restrict__ Wd,
                            const float* __restrict__ bih1,  const float* __restrict__ bhh1,
                            const float* __restrict__ bih2,  const float* __restrict__ bhh2)
{
    int i = blockIdx.x*blockDim.x + threadIdx.x;
    int n = gridDim.x*blockDim.x;
    for (int idx=i; idx<Fd*Ed; idx+=n){ int f=idx/Ed, e=idx%Ed; g_encwT[idx] = enc_w[e*Fd + f]; }
    for (int idx=i; idx<Ed*4*Hd; idx+=n){ int e=idx>>9, j=idx&511; g_W1gT[idx] = Wih1[j*Ed + e]*gamma[e]; }
    for (int idx=i; idx<Ed*Fd; idx+=n){ int e=idx>>9, f=idx&511; g_decwT[idx] = dec_w[f*Ed + e]; }
    for (int idx=i; idx<Hd*Ed; idx+=n){ int h=idx>>8, e=idx&255; g_WdT[idx] = Wd[e*Hd + h]; }
    for (int j=i; j<4*Hd; j+=n) g_bias2[j] = bih2[j] + bhh2[j];
    int wid = i >> 5, lane = i & 31;
    for (int j=wid; j<4*Hd; j += n>>5){
        float s = 0.f, cs = 0.f;
        for (int e=lane; e<Ed; e+=32){
            float w = Wih1[j*Ed + e];
            s  += beta[e]*w;
            cs += gamma[e]*w;
        }
        #pragma unroll
        for (int o=16;o>0;o>>=1){
            s  += __shfl_xor_sync(0xffffffffu, s, o);
            cs += __shfl_xor_sync(0xffffffffu, cs, o);
        }
        if (lane==0){
            g_bias1[j]  = s + bih1[j] + bhh1[j];
            g_colsum[j] = cs;
        }
    }
}

// ---------------- enc GEMM (R7 proven) ----------------
__global__ void __launch_bounds__(256) enc_kernel(const float* __restrict__ y1)
{
    __shared__ __align__(16) float As[2][16][128];
    __shared__ __align__(16) float Bs[2][16][64];
    const int b = blockIdx.z;
    const int t0 = blockIdx.x*128, e0 = blockIdx.y*64;
    const int tid = threadIdx.x;
    const int lk = tid>>4, lt = (tid&15)*8;
    const int bk = tid>>4, bn = (tid&15)*4;
    const int ty = tid>>4, tx = tid&15;
    const float* yb = y1 + (size_t)b*Fd*Td;
    u64 acc[8][2] = {};
    float4 ra0, ra1, rb0;
    {
        int t = t0 + lt;
        ra0 = make_float4(0.f,0.f,0.f,0.f); ra1 = ra0;
        if (t   < Td) ra0 = *(const float4*)(yb + (size_t)lk*Td + t);
        if (t+4 < Td) ra1 = *(const float4*)(yb + (size_t)lk*Td + t + 4);
        rb0 = *(const float4*)(g_encwT + (size_t)bk*Ed + e0 + bn);
        *(float4*)&As[0][lk][lt]   = ra0;
        *(float4*)&As[0][lk][lt+4] = ra1;
        *(float4*)&Bs[0][bk][bn]   = rb0;
    }
    __syncthreads();
    int cur = 0;
    for (int k0=0;k0<Fd;k0+=16){
        const bool more = (k0+16 < Fd);
        if (more){
            int k = k0 + 16 + lk;
            int t = t0 + lt;
            ra0 = make_float4(0.f,0.f,0.f,0.f); ra1 = ra0;
            if (t   < Td) ra0 = *(const float4*)(yb + (size_t)k*Td + t);
            if (t+4 < Td) ra1 = *(const float4*)(yb + (size_t)k*Td + t + 4);
            rb0 = *(const float4*)(g_encwT + (size_t)(k0+16+bk)*Ed + e0 + bn);
        }
        #pragma unroll
        for (int kk=0;kk<16;kk++){
            ulonglong2 bp = *(const ulonglong2*)&Bs[cur][kk][tx*4];
            float4 a0 = *(const float4*)&As[cur][kk][ty*8];
            float4 a1 = *(const float4*)&As[cur][kk][ty*8+4];
            u64 d0=packdup(a0.x), d1=packdup(a0.y), d2=packdup(a0.z), d3=packdup(a0.w);
            u64 d4=packdup(a1.x), d5=packdup(a1.y), d6=packdup(a1.z), d7=packdup(a1.w);
            ffma2(acc[0][0],d0,bp.x); ffma2(acc[0][1],d0,bp.y);
            ffma2(acc[1][0],d1,bp.x); ffma2(acc[1][1],d1,bp.y);
            ffma2(acc[2][0],d2,bp.x); ffma2(acc[2][1],d2,bp.y);
            ffma2(acc[3][0],d3,bp.x); ffma2(acc[3][1],d3,bp.y);
            ffma2(acc[4][0],d4,bp.x); ffma2(acc[4][1],d4,bp.y);
            ffma2(acc[5][0],d5,bp.x); ffma2(acc[5][1],d5,bp.y);
            ffma2(acc[6][0],d6,bp.x); ffma2(acc[6][1],d6,bp.y);
            ffma2(acc[7][0],d7,bp.x); ffma2(acc[7][1],d7,bp.y);
        }
        if (more){
            int nb = cur^1;
            *(float4*)&As[nb][lk][lt]   = ra0;
            *(float4*)&As[nb][lk][lt+4] = ra1;
            *(float4*)&Bs[nb][bk][bn]   = rb0;
        }
        __syncthreads();
        cur ^= 1;
    }
    #pragma unroll
    for (int i=0;i<8;i++){
        int t = t0 + ty*8 + i;
        if (t < Td){
            float4 v;
            unpk(v.x, v.y, acc[i][0]);
            unpk(v.z, v.w, acc[i][1]);
            *(float4*)(g_enc + ((size_t)b*Td + t)*Ed + e0 + tx*4) = v;
        }
    }
}

// ---------------- GEMM modes 0/1 (mode 0: fused layernorm) ----------------
__global__ void __launch_bounds__(256) gemm_kernel(
    const float* __restrict__ A, const float* __restrict__ Bm, float* __restrict__ C,
    const float* __restrict__ bias, const float* __restrict__ colsum,
    const float* __restrict__ encp, int K, int N, int mode)
{
    __shared__ __align__(16) float As[2][16][128];
    __shared__ __align__(16) float Bs[2][16][64];
    const int tid = threadIdx.x;
    const int m0 = blockIdx.x*128, n0 = blockIdx.y*64;
    const int ar = tid>>1, ak = (tid&1)*8;
    const int bk = tid>>4, bn = (tid&15)*4;
    const int ty = tid>>4, tx = tid&15;
    const float* Arow = A + (size_t)(m0+ar)*K;
    u64 acc[8][2] = {};
    float ssum = 0.f, sqsum = 0.f;
    float4 ra0, ra1, rb0;
    {
        ra0 = *(const float4*)(Arow + ak);
        ra1 = *(const float4*)(Arow + ak + 4);
        if (mode==0){
            ssum  += (ra0.x+ra0.y)+(ra0.z+ra0.w) + (ra1.x+ra1.y)+(ra1.z+ra1.w);
            sqsum += ra0.x*ra0.x+ra0.y*ra0.y+ra0.z*ra0.z+ra0.w*ra0.w
                   + ra1.x*ra1.x+ra1.y*ra1.y+ra1.z*ra1.z+ra1.w*ra1.w;
        }
        rb0 = *(const float4*)(Bm + (size_t)bk*N + n0 + bn);
        As[0][ak+0][ar]=ra0.x; As[0][ak+1][ar]=ra0.y; As[0][ak+2][ar]=ra0.z; As[0][ak+3][ar]=ra0.w;
        As[0][ak+4][ar]=ra1.x; As[0][ak+5][ar]=ra1.y; As[0][ak+6][ar]=ra1.z; As[0][ak+7][ar]=ra1.w;
        *(float4*)&Bs[0][bk][bn] = rb0;
    }
    __syncthreads();
    int cur = 0;
    for (int k0=0;k0<K;k0+=16){
        const bool more = (k0+16 < K);
        if (more){
            ra0 = *(const float4*)(Arow + k0+16 + ak);
            ra1 = *(const float4*)(Arow + k0+16 + ak + 4);
            if (mode==0){
                ssum  += (ra0.x+ra0.y)+(ra0.z+ra0.w) + (ra1.x+ra1.y)+(ra1.z+ra1.w);
                sqsum += ra0.x*ra0.x+ra0.y*ra0.y+ra0.z*ra0.z+ra0.w*ra0.w
                       + ra1.x*ra1.x+ra1.y*ra1.y+ra1.z*ra1.z+ra1.w*ra1.w;
            }
            rb0 = *(const float4*)(Bm + (size_t)(k0+16+bk)*N + n0 + bn);
        }
        #pragma unroll
        for (int kk=0;kk<16;kk++){
            ulonglong2 bp = *(const ulonglong2*)&Bs[cur][kk][tx*4];
            float4 a0 = *(const float4*)&As[cur][kk][ty*8];
            float4 a1 = *(const float4*)&As[cur][kk][ty*8+4];
            u64 d0=packdup(a0.x), d1=packdup(a0.y), d2=packdup(a0.z), d3=packdup(a0.w);
            u64 d4=packdup(a1.x), d5=packdup(a1.y), d6=packdup(a1.z), d7=packdup(a1.w);
            ffma2(acc[0][0],d0,bp.x); ffma2(acc[0][1],d0,bp.y);
            ffma2(acc[1][0],d1,bp.x); ffma2(acc[1][1],d1,bp.y);
            ffma2(acc[2][0],d2,bp.x); ffma2(acc[2][1],d2,bp.y);
            ffma2(acc[3][0],d3,bp.x); ffma2(acc[3][1],d3,bp.y);
            ffma2(acc[4][0],d4,bp.x); ffma2(acc[4][1],d4,bp.y);
            ffma2(acc[5][0],d5,bp.x); ffma2(acc[5][1],d5,bp.y);
            ffma2(acc[6][0],d6,bp.x); ffma2(acc[6][1],d6,bp.y);
            ffma2(acc[7][0],d7,bp.x); ffma2(acc[7][1],d7,bp.y);
        }
        if (more){
            int nb = cur^1;
            As[nb][ak+0][ar]=ra0.x; As[nb][ak+1][ar]=ra0.y; As[nb][ak+2][ar]=ra0.z; As[nb][ak+3][ar]=ra0.w;
            As[nb][ak+4][ar]=ra1.x; As[nb][ak+5][ar]=ra1.y; As[nb][ak+6][ar]=ra1.z; As[nb][ak+7][ar]=ra1.w;
            *(float4*)&Bs[nb][bk][bn] = rb0;
        }
        __syncthreads();
        cur ^= 1;
    }
    if (mode==0){
        float mu, rs;
        {
            float s2 = ssum  + __shfl_xor_sync(0xffffffffu, ssum, 1);
            float q2 = sqsum + __shfl_xor_sync(0xffffffffu, sqsum, 1);
            mu = s2 * (1.0f/256.0f);
            rs = rsqrtf(fmaf(-mu, mu, q2*(1.0f/256.0f)) + EPSf);
        }
        __shared__ float smu[128], srs[128];
        if ((tid&1)==0){ smu[ar] = mu; srs[ar] = rs; }
        __syncthreads();
        float4 bv = *(const float4*)(bias + n0 + tx*4);
        float4 sv = *(const float4*)(colsum + n0 + tx*4);
        #pragma unroll
        for (int i=0;i<8;i++){
            int mrow = ty*8 + i;
            float rmu = smu[mrow], rrs = srs[mrow];
            float4 v;
            unpk(v.x, v.y, acc[i][0]);
            unpk(v.z, v.w, acc[i][1]);
            v.x = fmaf(rrs, v.x - rmu*sv.x, bv.x);
            v.y = fmaf(rrs, v.y - rmu*sv.y, bv.y);
            v.z = fmaf(rrs, v.z - rmu*sv.z, bv.z);
            v.w = fmaf(rrs, v.w - rmu*sv.w, bv.w);
            *(float4*)(C + (size_t)(m0+mrow)*N + n0 + tx*4) = v;
        }
    } else {
        float4 bv = make_float4(0.f,0.f,0.f,0.f);
        if (bias) bv = *(const float4*)(bias + n0 + tx*4);
        #pragma unroll
        for (int i=0;i<8;i++){
            int m = m0 + ty*8 + i;
            float4 v;
            unpk(v.x, v.y, acc[i][0]);
            unpk(v.z, v.w, acc[i][1]);
            v.x += bv.x; v.y += bv.y; v.z += bv.z; v.w += bv.w;
            if (mode==1){
                float4 e = *(const float4*)(encp + (size_t)m*N + n0 + tx*4);
                v.x = sigf(v.x)*e.x; v.y = sigf(v.y)*e.y; v.z = sigf(v.z)*e.z; v.w = sigf(v.w)*e.w;
            }
            *(float4*)(C + (size_t)m*N + n0 + tx*4) = v;
        }
    }
}

// ---------------- decode GEMM (R7 proven) ----------------
__global__ void __launch_bounds__(256) dec_kernel(const float* __restrict__ A, float* __restrict__ C)
{
    __shared__ float buf[8256];
    float* AsB = buf;
    float* BsB = buf + 4096;
    const int b  = blockIdx.z;
    const int m0 = blockIdx.x*128;
    const int n0 = blockIdx.y*64;
    const int tid = threadIdx.x;
    const int ar = tid>>1, ak = (tid&1)*8;
    const int bk = tid>>4, bn = (tid&15)*4;
    const int ty = tid>>4, tx = tid&15;
    const float* Arow = A + ((size_t)b*Td + m0 + ar)*Ed;
    u64 acc[8][2] = {};
    float4 ra0, ra1, rb0;
    {
        ra0 = *(const float4*)(Arow + ak);
        ra1 = *(const float4*)(Arow + ak + 4);
        rb0 = *(const float4*)(g_decwT + (size_t)bk*Fd + n0 + bn);
        AsB[(ak+0)*128+ar]=ra0.x; AsB[(ak+1)*128+ar]=ra0.y; AsB[(ak+2)*128+ar]=ra0.z; AsB[(ak+3)*128+ar]=ra0.w;
        AsB[(ak+4)*128+ar]=ra1.x; AsB[(ak+5)*128+ar]=ra1.y; AsB[(ak+6)*128+ar]=ra1.z; AsB[(ak+7)*128+ar]=ra1.w;
        *(float4*)&BsB[bk*64 + bn] = rb0;
    }
    __syncthreads();
    int cur = 0;
    for (int k0=0;k0<Ed;k0+=16){
        const bool more = (k0+16 < Ed);
        if (more){
            ra0 = *(const float4*)(Arow + k0+16 + ak);
            ra1 = *(const float4*)(Arow + k0+16 + ak + 4);
            rb0 = *(const float4*)(g_decwT + (size_t)(k0+16+bk)*Fd + n0 + bn);
        }
        const float* asb = &AsB[cur*2048];
        const float* bsb = &BsB[cur*1024];
        #pragma unroll
        for (int kk=0;kk<16;kk++){
            ulonglong2 bp = *(const ulonglong2*)&bsb[kk*64 + tx*4];
            float4 a0 = *(const float4*)&asb[kk*128 + ty*8];
            float4 a1 = *(const float4*)&asb[kk*128 + ty*8 + 4];
            u64 d0=packdup(a0.x), d1=packdup(a0.y), d2=packdup(a0.z), d3=packdup(a0.w);
            u64 d4=packdup(a1.x), d5=packdup(a1.y), d6=packdup(a1.z), d7=packdup(a1.w);
            ffma2(acc[0][0],d0,bp.x); ffma2(acc[0][1],d0,bp.y);
            ffma2(acc[1][0],d1,bp.x); ffma2(acc[1][1],d1,bp.y);
            ffma2(acc[2][0],d2,bp.x); ffma2(acc[2][1],d2,bp.y);
            ffma2(acc[3][0],d3,bp.x); ffma2(acc[3][1],d3,bp.y);
            ffma2(acc[4][0],d4,bp.x); ffma2(acc[4][1],d4,bp.y);
            ffma2(acc[5][0],d5,bp.x); ffma2(acc[5][1],d5,bp.y);
            ffma2(acc[6][0],d6,bp.x); ffma2(acc[6][1],d6,bp.y);
            ffma2(acc[7][0],d7,bp.x); ffma2(acc[7][1],d7,bp.y);
        }
        if (more){
            int nb = cur^1;
            float* ap = &AsB[nb*2048];
            ap[(ak+0)*128+ar]=ra0.x; ap[(ak+1)*128+ar]=ra0.y; ap[(ak+2)*128+ar]=ra0.z; ap[(ak+3)*128+ar]=ra0.w;
            ap[(ak+4)*128+ar]=ra1.x; ap[(ak+5)*128+ar]=ra1.y; ap[(ak+6)*128+ar]=ra1.z; ap[(ak+7)*128+ar]=ra1.w;
            *(float4*)&BsB[nb*1024 + bk*64 + bn] = rb0;
        }
        __syncthreads();
        cur ^= 1;
    }
    __syncthreads();
    #pragma unroll
    for (int i=0;i<8;i++){
        float v0,v1,v2,v3;
        unpk(v0,v1,acc[i][0]); unpk(v2,v3,acc[i][1]);
        int ml = ty*8 + i;
        buf[(tx*4+0)*129 + ml] = v0;
        buf[(tx*4+1)*129 + ml] = v1;
        buf[(tx*4+2)*129 + ml] = v2;
        buf[(tx*4+3)*129 + ml] = v3;
    }
    __syncthreads();
    {
        int f = tid>>2;
        int seg = (tid&3)*32;
        float* crow = C + ((size_t)b*Fd + n0 + f)*Td;
        const float* trow = &buf[f*129 + seg];
        #pragma unroll
        for (int q=0;q<8;q++){
            int t = m0 + seg + q*4;
            if (t < Td){
                float4 v = make_float4(trow[q*4+0], trow[q*4+1], trow[q*4+2], trow[q*4+3]);
                *(float4*)(crow + t) = v;
            }
        }
    }
}

// ---------------- LSTM scan v7: R9 protocol, h2 gates moved to warp 8 (tau2) ----------------
__global__ void __launch_bounds__(384,1) __cluster_dims__(4,1,1)
lstm_kernel(const float* __restrict__ in_state2,
            const float* __restrict__ Whh1, const float* __restrict__ Wih2,
            const float* __restrict__ Whh2, float* __restrict__ out_state)
{
    __shared__ __align__(16) u64   mbH1[2], mbH2[2];
    __shared__ __align__(16) float h1b[2][128];
    __shared__ __align__(16) float h2b[2][128];
    __shared__ __align__(16) float h1loc[128];
    __shared__ __align__(16) float zp1[2][128];
    __shared__ __align__(16) float zp2[2][3][128];

    const int tid  = threadIdx.x;
    const int rank = blockIdx.x & 3, b = blockIdx.x >> 2;
    const int tau  = tid >> 7, row = tid & 127;
    const int gate = row >> 5, u = row & 31;
    const int Rg = gate*128 + rank*32 + u;

    const uint32_t mh1_0 = smem_u32(&mbH1[0]);
    const uint32_t mh1_1 = smem_u32(&mbH1[1]);
    const uint32_t mh2_0 = smem_u32(&mbH2[0]);
    const uint32_t mh2_1 = smem_u32(&mbH2[1]);

    if (tid == 0){
        mbar_init(mh1_0, 1); mbar_init(mh1_1, 1);
        mbar_init(mh2_0, 1); mbar_init(mh2_1, 1);
        mbar_arrive_expect(mh1_0, 512);
        mbar_arrive_expect(mh1_1, 512);
        mbar_arrive_expect(mh2_0, 512);
        mbar_arrive_expect(mh2_1, 512);
    }

    u64 Ar[32], Br[32];
    {
        const float *pA, *pB;
        if (tau == 0){ pA = Whh1 + (size_t)Rg*Hd;      pB = Wih2 + (size_t)Rg*Hd; }
        else if (tau == 1){ pA = Whh1 + (size_t)Rg*Hd + 64; pB = Wih2 + (size_t)Rg*Hd + 64; }
        else { pA = Whh2 + (size_t)Rg*Hd;              pB = Whh2 + (size_t)Rg*Hd + 64; }
        const u64* qa = (const u64*)pA;
        const u64* qb = (const u64*)pB;
        #pragma unroll
        for (int k=0;k<32;k++){ Ar[k] = qa[k]; Br[k] = qb[k]; }
    }
    if (tau == 0){
        h1b[1][row] = in_state2[(((size_t)0*Bn + b)*Hd + row)*2 + 0];
        h2b[0][row] = in_state2[(((size_t)1*Bn + b)*Hd + row)*2 + 0];
    }
    const float b2r = g_bias2[Rg];

    float c1=0.f, c2=0.f, h1v=0.f, h2v=0.f;
    int hh = 0;
    const bool is_l1  = (tid >= 32 && tid < 64);          // h1 gates (warp1, tau0)
    const bool is_l2g = (tid >= 256 && tid < 288);        // h2 gates (warp8, tau2)
    uint32_t dstA[2][4], rbA[2][4];
    if (is_l2g || is_l1){
        int uu = is_l2g ? (tid-256) : (tid-32);
        hh = rank*32 + uu;
        uint32_t la_h = is_l2g ? smem_u32(&h2b[0][hh]) : smem_u32(&h1b[0][hh]);
        #pragma unroll
        for (int s=0;s<2;s++){
            uint32_t mbs = is_l2g ? (s ? mh2_1 : mh2_0) : (s ? mh1_1 : mh1_0);
            #pragma unroll
            for (int r=0;r<4;r++){
                dstA[s][r] = mapa_rank(la_h + s*512, (uint32_t)r);
                rbA[s][r]  = mapa_rank(mbs, (uint32_t)r);
            }
        }
        if (is_l2g) c2 = in_state2[(((size_t)1*Bn + b)*Hd + hh)*2 + 1];
        else        c1 = in_state2[(((size_t)0*Bn + b)*Hd + hh)*2 + 1];
    }
    __syncthreads();
    cluster_sync();

    const float* zrow = g_zpre + (size_t)b*Td*512 + Rg;
    float* ys2row = g_ys2 + (size_t)b*Td*Hd;
    float zp_cur = 0.f;
    if (tau == 0) zp_cur = zrow[512];

    // ---- prologue: h1[0] from h1b[1] ----
    if (tau < 2){
        float zp0 = (tau==0) ? zrow[0] : 0.f;
        const ulonglong2* xa = (const ulonglong2*)&h1b[1][tau*64];
        u64 a1 = 0, a2 = 0;
        #pragma unroll
        for (int k=0;k<16;k++){
            ulonglong2 x = xa[k];
            ffma2(a1, Ar[2*k],   x.x);
            ffma2(a2, Ar[2*k+1], x.y);
        }
        zp1[tau][row] = upsum(a1, a2) + zp0;
        bar_sync_1_256();
        if (is_l1){
            int uu = tid-32;
            float zi = zp1[0][uu]    + zp1[1][uu];
            float zf = zp1[0][32+uu] + zp1[1][32+uu];
            float zg = zp1[0][64+uu] + zp1[1][64+uu];
            float zo = zp1[0][96+uu] + zp1[1][96+uu];
            c1 = fsig(zf)*c1 + fsig(zi)*ftanh(zg);
            h1v = fsig(zo)*ftanh(c1);
            #pragma unroll
            for (int r=0;r<4;r++) st_async_f32(dstA[0][r], h1v, rbA[0][r]);
        }
    }
    int phH1[2] = {0,0}, phH2[2] = {0,0};
    if (tid < 256){
        mbar_wait(mh1_0, 0); phH1[0] = 1;
        if (tid == 128) mbar_arrive_expect(mh1_0, 512);
    }

    // ---- main loop ----
    for (int t=0; t<Td; t++){
        const int p = t & 1, q = p ^ 1;
        float zp_next = 0.f;
        if (tau == 0){
            int tn = t + 2; if (tn > Td-1) tn = Td-1;
            zp_next = __ldg(zrow + (size_t)tn*512);
        }

        if (tau < 2){
            if (tid < 32){
                *(float4*)&h1loc[tid*4] = *(const float4*)&h1b[p][tid*4];
            }
            const ulonglong2* xa = (const ulonglong2*)&h1b[p][tau*64];
            u64 a1=0, a2=0;
            #pragma unroll
            for (int k=0;k<16;k++){
                ulonglong2 x = xa[k];
                ffma2(a1, Ar[2*k],   x.x);
                ffma2(a2, Ar[2*k+1], x.y);
            }
            zp1[tau][row] = upsum(a1, a2) + ((tau==0) ? zp_cur : 0.f);
            bar_sync_1_256();
            if (is_l1){
                int uu = tid-32;
                float zi = zp1[0][uu]    + zp1[1][uu];
                float zf = zp1[0][32+uu] + zp1[1][32+uu];
                float zg = zp1[0][64+uu] + zp1[1][64+uu];
                float zo = zp1[0][96+uu] + zp1[1][96+uu];
                if (t < Td-1){
                    c1 = fsig(zf)*c1 + fsig(zi)*ftanh(zg);
                    h1v = fsig(zo)*ftanh(c1);
                }
                #pragma unroll
                for (int r=0;r<4;r++) st_async_f32(dstA[q][r], h1v, rbA[q][r]);
            }
            {
                const ulonglong2* xb = (const ulonglong2*)&h1loc[tau*64];
                u64 b1=0, b2a=0;
                #pragma unroll
                for (int k=0;k<16;k++){
                    ulonglong2 x = xb[k];
                    ffma2(b1,  Br[2*k],   x.x);
                    ffma2(b2a, Br[2*k+1], x.y);
                }
                zp2[p][tau][row] = upsum(b1, b2a);
            }
        } else {
            const ulonglong2* xa = (const ulonglong2*)&h2b[p][0];
            const ulonglong2* xb = (const ulonglong2*)&h2b[p][64];
            u64 a1=0, a2=0, b1=0, b2a=0;
            #pragma unroll
            for (int k=0;k<16;k++){
                ulonglong2 x = xa[k], y = xb[k];
                ffma2(a1,  Ar[2*k],   x.x);
                ffma2(a2,  Ar[2*k+1], x.y);
                ffma2(b1,  Br[2*k],   y.x);
                ffma2(b2a, Br[2*k+1], y.y);
            }
            zp2[p][2][row] = upsum(a1, a2) + upsum(b1, b2a) + b2r;
        }
        __syncthreads();

        if (is_l2g){
            int uu = tid-256;
            float zi = zp2[p][0][uu]    + zp2[p][1][uu]    + zp2[p][2][uu];
            float zf = zp2[p][0][32+uu] + zp2[p][1][32+uu] + zp2[p][2][32+uu];
            float zg = zp2[p][0][64+uu] + zp2[p][1][64+uu] + zp2[p][2][64+uu];
            float zo = zp2[p][0][96+uu] + zp2[p][1][96+uu] + zp2[p][2][96+uu];
            c2 = fsig(zf)*c2 + fsig(zi)*ftanh(zg);
            h2v = fsig(zo)*ftanh(c2);
            #pragma unroll
            for (int r=0;r<4;r++) st_async_f32(dstA[q][r], h2v, rbA[q][r]);
            ys2row[(size_t)t*Hd + hh] = h2v;
        }

        if (tid < 256){
            uint32_t mb = q ? mh1_1 : mh1_0;
            mbar_wait(mb, phH1[q]); phH1[q] ^= 1;
            if (tid == 128) mbar_arrive_expect(mb, 512);
        } else {
            uint32_t mb = q ? mh2_1 : mh2_0;
            mbar_wait(mb, phH2[q]); phH2[q] ^= 1;
            if (tid == 256) mbar_arrive_expect(mb, 512);
        }
        zp_cur = zp_next;
    }

    if (is_l2g){
        out_state[(((size_t)1*Bn + b)*Hd + hh)*2 + 0] = h2v;
        out_state[(((size_t)1*Bn + b)*Hd + hh)*2 + 1] = c2;
    } else if (is_l1){
        out_state[(((size_t)0*Bn + b)*Hd + hh)*2 + 0] = h1v;
        out_state[(((size_t)0*Bn + b)*Hd + hh)*2 + 1] = c1;
    }
}

// ---------------- launcher ----------------
extern "C" void kernel_launch(void* const* d_in, const int* in_sizes, int n_in,
                              void* d_out, int out_size)
{
    const float* y1        = (const float*)d_in[0];
    const float* in_state2 = (const float*)d_in[1];
    const float* enc_w     = (const float*)d_in[2];
    const float* gamma     = (const float*)d_in[3];
    const float* beta      = (const float*)d_in[4];
    const float* Wih1      = (const float*)d_in[5];
    const float* Whh1      = (const float*)d_in[6];
    const float* bih1      = (const float*)d_in[7];
    const float* bhh1      = (const float*)d_in[8];
    const float* Wih2      = (const float*)d_in[9];
    const float* Whh2      = (const float*)d_in[10];
    const float* bih2      = (const float*)d_in[11];
    const float* bhh2      = (const float*)d_in[12];
    const float* Wd        = (const float*)d_in[13];
    const float* bd        = (const float*)d_in[14];
    const float* dec_w     = (const float*)d_in[15];
    float* out = (float*)d_out;

    void *encp, *zp, *ys2p, *w1gt, *wdt, *b1p, *csp;
    cudaGetSymbolAddress(&encp,  g_enc);
    cudaGetSymbolAddress(&zp,    g_zpre);
    cudaGetSymbolAddress(&ys2p,  g_ys2);
    cudaGetSymbolAddress(&w1gt,  g_W1gT);
    cudaGetSymbolAddress(&wdt,   g_WdT);
    cudaGetSymbolAddress(&b1p,   g_bias1);
    cudaGetSymbolAddress(&csp,   g_colsum);

    prep_kernel<<<64,256>>>(enc_w,gamma,beta,Wih1,dec_w,Wd,bih1,bhh1,bih2,bhh2);
    enc_kernel<<<dim3(16,4,32),256>>>(y1);
    gemm_kernel<<<dim3(500,8),256>>>((const float*)encp, (const float*)w1gt, (float*)zp,
                                     (const float*)b1p, (const float*)csp,
                                     nullptr, 256, 512, 0);
    {
        float* outstate = out + (size_t)Bn*Fd*Td;
        lstm_kernel<<<Bn*4, 384>>>(in_state2, Whh1, Wih2, Whh2, outstate);
    }
    gemm_kernel<<<dim3(500,4),256>>>((const float*)ys2p, (const float*)wdt, (float*)zp,
                                     bd, nullptr, (const float*)encp, 128, 256, 1);
    dec_kernel<<<dim3(16,8,32),256>>>((const float*)zp, out);
}